// round 14
// baseline (speedup 1.0000x reference)
#include <cuda_runtime.h>
#include <cuda_fp16.h>
#include <cstdint>
#include <cfloat>

#define DEVI __device__ __forceinline__

static constexpr int BATCH  = 4;
static constexpr int SEQ    = 2048;
static constexpr int DMODEL = 512;
static constexpr int NH     = 8;
static constexpr int DH     = 64;
static constexpr int ROWS   = BATCH * SEQ;          // 8192

// Scratch (allocation-free rule: device globals)
__device__ __align__(16) __half   g_xq[ROWS * DMODEL];
__device__ __align__(16) __half   g_xk[ROWS * DMODEL];
__device__ __align__(16) __half   g_xv[ROWS * DMODEL];
__device__ __align__(16) __half   g_wq[DMODEL * DMODEL];
__device__ __align__(16) __half   g_wk[DMODEL * DMODEL];
__device__ __align__(16) __half   g_wv[DMODEL * DMODEL];
__device__ __align__(16) __half   g_wo[DMODEL * DMODEL];
__device__ __align__(16) __half   g_q[BATCH * NH * SEQ * DH];
__device__ __align__(16) __half   g_k[BATCH * NH * SEQ * DH];
__device__ __align__(16) __half   g_v[BATCH * NH * SEQ * DH];
__device__ __align__(16) __half   g_ctx[ROWS * DMODEL];
__device__            unsigned    g_maskp[BATCH * SEQ * (SEQ / 32)];

// ---------------------------------------------------------------- helpers

DEVI uint32_t smaddr(const void* p) { return (uint32_t)__cvta_generic_to_shared(p); }

DEVI void ldsm4(uint32_t r[4], const void* p) {
    uint32_t a = smaddr(p);
    asm volatile("ldmatrix.sync.aligned.m8n8.x4.shared.b16 {%0,%1,%2,%3}, [%4];"
                 : "=r"(r[0]), "=r"(r[1]), "=r"(r[2]), "=r"(r[3]) : "r"(a));
}
DEVI void ldsm4t(uint32_t r[4], const void* p) {
    uint32_t a = smaddr(p);
    asm volatile("ldmatrix.sync.aligned.m8n8.x4.trans.shared.b16 {%0,%1,%2,%3}, [%4];"
                 : "=r"(r[0]), "=r"(r[1]), "=r"(r[2]), "=r"(r[3]) : "r"(a));
}

DEVI void mma16816(float c[4], const uint32_t a[4], uint32_t b0, uint32_t b1) {
    asm volatile(
        "mma.sync.aligned.m16n8k16.row.col.f32.f16.f16.f32 "
        "{%0,%1,%2,%3}, {%4,%5,%6,%7}, {%8,%9}, {%0,%1,%2,%3};"
        : "+f"(c[0]), "+f"(c[1]), "+f"(c[2]), "+f"(c[3])
        : "r"(a[0]), "r"(a[1]), "r"(a[2]), "r"(a[3]), "r"(b0), "r"(b1));
}

DEVI uint32_t f2h2(float x, float y) {
    __half2 h = __floats2half2_rn(x, y);
    return *reinterpret_cast<uint32_t*>(&h);
}

DEVI uint32_t hex2(uint32_t x) {        // ex2 on packed half2 (one MUFU op, two values)
    uint32_t y;
    asm("ex2.approx.f16x2 %0, %1;" : "=r"(y) : "r"(x));
    return y;
}

DEVI void cpa16(void* dst, const void* src) {
    asm volatile("cp.async.cg.shared.global [%0], [%1], 16;" :: "r"(smaddr(dst)), "l"(src));
}
DEVI void cpa4(void* dst, const void* src) {
    asm volatile("cp.async.ca.shared.global [%0], [%1], 4;" :: "r"(smaddr(dst)), "l"(src));
}
DEVI void cpcommit() { asm volatile("cp.async.commit_group;"); }
DEVI void cpwait0()  { asm volatile("cp.async.wait_group 0;"); }

// ---------------------------------------------------------------- prep: fp32->fp16 converts ONLY

__global__ __launch_bounds__(256) void prep_kernel(
    const float* __restrict__ Q, const float* __restrict__ K, const float* __restrict__ V,
    const float* __restrict__ Wq, const float* __restrict__ Wk,
    const float* __restrict__ Wv, const float* __restrict__ Wo)
{
    int blk = blockIdx.x;
    const float* src; __half* dst; int off;
    if      (blk < 2048) { src = Q;  dst = g_xq; off = blk; }
    else if (blk < 4096) { src = K;  dst = g_xk; off = blk - 2048; }
    else if (blk < 6144) { src = V;  dst = g_xv; off = blk - 4096; }
    else if (blk < 6272) { src = Wq; dst = g_wq; off = blk - 6144; }
    else if (blk < 6400) { src = Wk; dst = g_wk; off = blk - 6272; }
    else if (blk < 6528) { src = Wv; dst = g_wv; off = blk - 6400; }
    else                 { src = Wo; dst = g_wo; off = blk - 6528; }
    int base = off * 2048 + threadIdx.x * 8;
    float4 v0 = *reinterpret_cast<const float4*>(&src[base]);
    float4 v1 = *reinterpret_cast<const float4*>(&src[base + 4]);
    __half2 h[4] = { __floats2half2_rn(v0.x, v0.y), __floats2half2_rn(v0.z, v0.w),
                     __floats2half2_rn(v1.x, v1.y), __floats2half2_rn(v1.z, v1.w) };
    *reinterpret_cast<uint4*>(&dst[base]) = *reinterpret_cast<uint4*>(h);
}

// ---------------------------------------------------------------- QKV GEMM + mask pack (z = 0..2 gemm, z = 3 mask)
// C[8192,512] = X * W + bias -> fp16 scattered to [b,h,s,d]. z==0 folds 0.125*log2e.
// CTA tile 128x128, BK=32, 256 threads, 2-stage cp.async double buffer.
// z==3 slice (256 CTAs): pack mask int32 -> bits; DRAM-bound work overlapping
// the tensor-bound GEMM slices in the same launch.

__global__ __launch_bounds__(256) void qkv_kernel(
    const int* __restrict__ mask,
    const __half* __restrict__ A0, const __half* __restrict__ A1, const __half* __restrict__ A2,
    const __half* __restrict__ W0, const __half* __restrict__ W1, const __half* __restrict__ W2,
    const float* __restrict__ b0p, const float* __restrict__ b1p, const float* __restrict__ b2p)
{
    __shared__ __half sA[2][128 * 40];
    __shared__ __half sB[2][32 * 136];

    int tid = threadIdx.x, l = tid & 31, w = tid >> 5;
    int z = blockIdx.z;

    if (z == 3) {           // ---- mask packing slice: 256 CTAs x 2048 words
        int cta = blockIdx.x * 4 + blockIdx.y;          // 0..255
#pragma unroll
        for (int i = 0; i < 8; i++) {
            int wi = cta * 2048 + i * 256 + tid;
            const int4* p = reinterpret_cast<const int4*>(mask) + wi * 8;
            unsigned bits = 0;
#pragma unroll
            for (int j = 0; j < 8; j++) {
                int4 v = p[j];
                bits |= (v.x != 0 ? 1u : 0u) << (j * 4 + 0);
                bits |= (v.y != 0 ? 1u : 0u) << (j * 4 + 1);
                bits |= (v.z != 0 ? 1u : 0u) << (j * 4 + 2);
                bits |= (v.w != 0 ? 1u : 0u) << (j * 4 + 3);
            }
            g_maskp[wi] = bits;
        }
        return;
    }

    int wm = w >> 1, wn = w & 1;
    int m0 = blockIdx.x * 128, n0 = blockIdx.y * 128;
    const __half* A = (z == 0) ? A0 : (z == 1) ? A1 : A2;
    const __half* W = (z == 0) ? W0 : (z == 1) ? W1 : W2;
    const float* bias = (z == 0) ? b0p : (z == 1) ? b1p : b2p;

    float o[2][8][4];
#pragma unroll
    for (int mb = 0; mb < 2; mb++)
#pragma unroll
        for (int i = 0; i < 8; i++)
#pragma unroll
            for (int j = 0; j < 4; j++) o[mb][i][j] = 0.f;

    {  // prefetch stage 0
#pragma unroll
        for (int i = 0; i < 2; i++) {
            int c = tid + i * 256; int r = c >> 2, cc = (c & 3) * 8;
            cpa16(&sA[0][r * 40 + cc], &A[(m0 + r) * 512 + cc]);
        }
#pragma unroll
        for (int i = 0; i < 2; i++) {
            int c = tid + i * 256; int r = c >> 4, cc = (c & 15) * 8;
            cpa16(&sB[0][r * 136 + cc], &W[r * 512 + n0 + cc]);
        }
        cpcommit();
    }

    for (int t = 0; t < 16; t++) {
        cpwait0();
        __syncthreads();
        if (t < 15) {
            int buf = (t + 1) & 1, t1 = t + 1;
#pragma unroll
            for (int i = 0; i < 2; i++) {
                int c = tid + i * 256; int r = c >> 2, cc = (c & 3) * 8;
                cpa16(&sA[buf][r * 40 + cc], &A[(m0 + r) * 512 + t1 * 32 + cc]);
            }
#pragma unroll
            for (int i = 0; i < 2; i++) {
                int c = tid + i * 256; int r = c >> 4, cc = (c & 15) * 8;
                cpa16(&sB[buf][r * 136 + cc], &W[(t1 * 32 + r) * 512 + n0 + cc]);
            }
            cpcommit();
        }
        const __half* a_ = sA[t & 1];
        const __half* b_ = sB[t & 1];
#pragma unroll
        for (int kk = 0; kk < 2; kk++) {
            uint32_t af[2][4];
#pragma unroll
            for (int mb = 0; mb < 2; mb++)
                ldsm4(af[mb], &a_[(wm * 32 + mb * 16 + (l % 16)) * 40 + kk * 16 + 8 * (l / 16)]);
#pragma unroll
            for (int nb = 0; nb < 4; nb++) {
                uint32_t bf[4];
                ldsm4t(bf, &b_[(kk * 16 + (l % 8) + 8 * ((l >> 3) & 1)) * 136 + wn * 64 + nb * 16 + 8 * (l >> 4)]);
#pragma unroll
                for (int mb = 0; mb < 2; mb++) {
                    mma16816(o[mb][2 * nb + 0], af[mb], bf[0], bf[1]);
                    mma16816(o[mb][2 * nb + 1], af[mb], bf[2], bf[3]);
                }
            }
        }
    }

    int t2 = (l & 3) * 2;
    __half* dst = (z == 0) ? g_q : (z == 1) ? g_k : g_v;
    float s = (z == 0) ? 0.1803368801111204f : 1.f;   // 1/sqrt(64)*log2(e) folded into q
    int h = (n0 + wn * 64) >> 6;
#pragma unroll
    for (int mb = 0; mb < 2; mb++) {
        int ra = m0 + wm * 32 + mb * 16 + (l >> 2);
        int rb = ra + 8;
        int ba = ra >> 11, sa = ra & 2047;
        int bb = rb >> 11, sb = rb & 2047;
#pragma unroll
        for (int n8 = 0; n8 < 8; n8++) {
            int c = n0 + wn * 64 + n8 * 8 + t2;
            int d = c & 63;
            float c0 = bias[c], c1 = bias[c + 1];
            int ia = (((ba << 3) + h) * SEQ + sa) * DH + d;
            int ib = (((bb << 3) + h) * SEQ + sb) * DH + d;
            *reinterpret_cast<__half2*>(&dst[ia]) =
                __floats2half2_rn((o[mb][n8][0] + c0) * s, (o[mb][n8][1] + c1) * s);
            *reinterpret_cast<__half2*>(&dst[ib]) =
                __floats2half2_rn((o[mb][n8][2] + c0) * s, (o[mb][n8][3] + c1) * s);
        }
    }
}

// ---------------------------------------------------------------- output projection
// out = ctx[8192,512](fp16) * Wo + bo -> fp32

__global__ __launch_bounds__(256) void oproj_kernel(
    const __half* __restrict__ A, const __half* __restrict__ W,
    const float* __restrict__ bias, float* __restrict__ outf)
{
    __shared__ __half sA[2][128 * 40];
    __shared__ __half sB[2][32 * 136];

    int tid = threadIdx.x, l = tid & 31, w = tid >> 5;
    int wm = w >> 1, wn = w & 1;
    int m0 = blockIdx.x * 128, n0 = blockIdx.y * 128;

    float o[2][8][4];
#pragma unroll
    for (int mb = 0; mb < 2; mb++)
#pragma unroll
        for (int i = 0; i < 8; i++)
#pragma unroll
            for (int j = 0; j < 4; j++) o[mb][i][j] = 0.f;

    {
#pragma unroll
        for (int i = 0; i < 2; i++) {
            int c = tid + i * 256; int r = c >> 2, cc = (c & 3) * 8;
            cpa16(&sA[0][r * 40 + cc], &A[(m0 + r) * 512 + cc]);
        }
#pragma unroll
        for (int i = 0; i < 2; i++) {
            int c = tid + i * 256; int r = c >> 4, cc = (c & 15) * 8;
            cpa16(&sB[0][r * 136 + cc], &W[r * 512 + n0 + cc]);
        }
        cpcommit();
    }

    for (int t = 0; t < 16; t++) {
        cpwait0();
        __syncthreads();
        if (t < 15) {
            int buf = (t + 1) & 1, t1 = t + 1;
#pragma unroll
            for (int i = 0; i < 2; i++) {
                int c = tid + i * 256; int r = c >> 2, cc = (c & 3) * 8;
                cpa16(&sA[buf][r * 40 + cc], &A[(m0 + r) * 512 + t1 * 32 + cc]);
            }
#pragma unroll
            for (int i = 0; i < 2; i++) {
                int c = tid + i * 256; int r = c >> 4, cc = (c & 15) * 8;
                cpa16(&sB[buf][r * 136 + cc], &W[(t1 * 32 + r) * 512 + n0 + cc]);
            }
            cpcommit();
        }
        const __half* a_ = sA[t & 1];
        const __half* b_ = sB[t & 1];
#pragma unroll
        for (int kk = 0; kk < 2; kk++) {
            uint32_t af[2][4];
#pragma unroll
            for (int mb = 0; mb < 2; mb++)
                ldsm4(af[mb], &a_[(wm * 32 + mb * 16 + (l % 16)) * 40 + kk * 16 + 8 * (l / 16)]);
#pragma unroll
            for (int nb = 0; nb < 4; nb++) {
                uint32_t bf[4];
                ldsm4t(bf, &b_[(kk * 16 + (l % 8) + 8 * ((l >> 3) & 1)) * 136 + wn * 64 + nb * 16 + 8 * (l >> 4)]);
#pragma unroll
                for (int mb = 0; mb < 2; mb++) {
                    mma16816(o[mb][2 * nb + 0], af[mb], bf[0], bf[1]);
                    mma16816(o[mb][2 * nb + 1], af[mb], bf[2], bf[3]);
                }
            }
        }
    }

    int t2 = (l & 3) * 2;
#pragma unroll
    for (int mb = 0; mb < 2; mb++) {
        int ra = m0 + wm * 32 + mb * 16 + (l >> 2);
        int rb = ra + 8;
#pragma unroll
        for (int n8 = 0; n8 < 8; n8++) {
            int c = n0 + wn * 64 + n8 * 8 + t2;
            float c0 = bias[c], c1 = bias[c + 1];
            *reinterpret_cast<float2*>(&outf[ra * 512 + c]) =
                make_float2(o[mb][n8][0] + c0, o[mb][n8][1] + c1);
            *reinterpret_cast<float2*>(&outf[rb * 512 + c]) =
                make_float2(o[mb][n8][2] + c0, o[mb][n8][3] + c1);
        }
    }
}

// ---------------------------------------------------------------- flash attention
// CTA: 128 q rows of one (b,h). 8 warps x 16 rows. BK=64 keys/iter, 32 iters.
// Constant-shift softmax. fp16x2 exponentials (select -> pack -> ex2.f16x2:
// halves the MUFU count), row sum via HADD2 accumulation of the packed p
// (per-iter sums <= ~40, fp16-safe; fp32 carries the cross-iter total).
// NO ones-MMA (round-12 showed +tensor ops at the plateau cancel the win).
// Smem arena [K0|V0|K1|V1]; Q staging aliases [K1|V1].

__global__ __launch_bounds__(256) void attn_kernel() {
    __shared__ __align__(16) __half sKV[4 * 64 * 72];   // 4608 halves per buffer
    __shared__ unsigned sM[2][256];

    int tid = threadIdx.x, l = tid & 31, w = tid >> 5;
    int q0 = blockIdx.x * 128, h = blockIdx.y, b = blockIdx.z;
    int bh = b * NH + h;
    const __half* gq = &g_q[(bh * SEQ + q0) * DH];

    __half* sQ = &sKV[2 * 4608];                        // aliases [K1|V1]

#pragma unroll
    for (int i = 0; i < 4; i++) {
        int e = tid + i * 256;
        int r = e >> 3, c = (e & 7) * 8;
        *reinterpret_cast<uint4*>(&sQ[r * 72 + c]) =
            *reinterpret_cast<const uint4*>(&gq[r * 64 + c]);
    }

    {   // prefetch stage 0 (K0/V0 — disjoint from sQ alias)
        const __half* gk = &g_k[(bh * SEQ) * DH];
        const __half* gv = &g_v[(bh * SEQ) * DH];
#pragma unroll
        for (int i = 0; i < 2; i++) {
            int c = tid + i * 256; int r = c >> 3, cc = (c & 7) * 8;
            cpa16(&sKV[0 * 4608 + r * 72 + cc], &gk[r * 64 + cc]);
            cpa16(&sKV[1 * 4608 + r * 72 + cc], &gv[r * 64 + cc]);
        }
        cpa4(&sM[0][tid], &g_maskp[(b * SEQ + q0 + (tid >> 1)) * (SEQ / 32) + (tid & 1)]);
        cpcommit();
    }
    __syncthreads();   // sQ visible

    uint32_t qa[4][4];
#pragma unroll
    for (int kk = 0; kk < 4; kk++)
        ldsm4(qa[kk], &sQ[(w * 16 + (l % 16)) * 72 + kk * 16 + 8 * (l / 16)]);

    __syncthreads();   // all threads done reading sQ before anyone writes buf1

    float o[8][4];
#pragma unroll
    for (int i = 0; i < 8; i++)
#pragma unroll
        for (int j = 0; j < 4; j++) o[i][j] = 0.f;
    float l_a = 0.f, l_b = 0.f;

    int ra_local = w * 16 + (l >> 2);
    int t2 = (l & 3) * 2;

    for (int kt = 0; kt < 32; kt++) {
        cpwait0();
        __syncthreads();
        if (kt < 31) {
            int buf = (kt + 1) & 1;
            const __half* gk = &g_k[(bh * SEQ + (kt + 1) * 64) * DH];
            const __half* gv = &g_v[(bh * SEQ + (kt + 1) * 64) * DH];
#pragma unroll
            for (int i = 0; i < 2; i++) {
                int c = tid + i * 256; int r = c >> 3, cc = (c & 7) * 8;
                cpa16(&sKV[(2 * buf + 0) * 4608 + r * 72 + cc], &gk[r * 64 + cc]);
                cpa16(&sKV[(2 * buf + 1) * 4608 + r * 72 + cc], &gv[r * 64 + cc]);
            }
            cpa4(&sM[buf][tid],
                 &g_maskp[(b * SEQ + q0 + (tid >> 1)) * (SEQ / 32) + (kt + 1) * 2 + (tid & 1)]);
            cpcommit();
        }
        const __half*   K_ = &sKV[(2 * (kt & 1) + 0) * 4608];
        const __half*   V_ = &sKV[(2 * (kt & 1) + 1) * 4608];
        const unsigned* M_ = sM[kt & 1];

        // S = Q K^T  (already includes 0.125*log2e via q)
        float sc[8][4];
#pragma unroll
        for (int i = 0; i < 8; i++)
#pragma unroll
            for (int j = 0; j < 4; j++) sc[i][j] = 0.f;
#pragma unroll
        for (int kk = 0; kk < 4; kk++) {
#pragma unroll
            for (int nb = 0; nb < 4; nb++) {
                uint32_t kf[4];
                ldsm4(kf, &K_[(nb * 16 + (l % 8) + 8 * (l >> 4)) * 72 + kk * 16 + 8 * ((l >> 3) & 1)]);
                mma16816(sc[2 * nb + 0], qa[kk], kf[0], kf[1]);
                mma16816(sc[2 * nb + 1], qa[kk], kf[2], kf[3]);
            }
        }

        // mask (select -> -64; exp2(-64) -> exact 0 in fp16), pack, ex2.f16x2.
        // Row sums accumulated in half2, spilled to fp32 once per iteration.
        unsigned ma0 = M_[ra_local * 2 + 0],       ma1 = M_[ra_local * 2 + 1];
        unsigned mb0 = M_[(ra_local + 8) * 2 + 0], mb1 = M_[(ra_local + 8) * 2 + 1];

        uint32_t pa[4][4];
        __half2 hs_a = __float2half2_rn(0.f);
        __half2 hs_b = __float2half2_rn(0.f);
#pragma unroll
        for (int n8 = 0; n8 < 8; n8++) {
            int col = n8 * 8 + t2;
            unsigned ba_ = ((col < 32) ? ma0 : ma1) >> (col & 31);
            unsigned bb_ = ((col < 32) ? mb0 : mb1) >> (col & 31);
            float a0 = (ba_ & 1) ? sc[n8][0] : -64.f;
            float a1 = (ba_ & 2) ? sc[n8][1] : -64.f;
            float b0 = (bb_ & 1) ? sc[n8][2] : -64.f;
            float b1 = (bb_ & 2) ? sc[n8][3] : -64.f;
            uint32_t pha = hex2(f2h2(a0, a1));
            uint32_t phb = hex2(f2h2(b0, b1));
            pa[n8 >> 1][(n8 & 1) * 2 + 0] = pha;
            pa[n8 >> 1][(n8 & 1) * 2 + 1] = phb;
            hs_a = __hadd2(hs_a, *reinterpret_cast<__half2*>(&pha));
            hs_b = __hadd2(hs_b, *reinterpret_cast<__half2*>(&phb));
        }
        l_a += __low2float(hs_a) + __high2float(hs_a);
        l_b += __low2float(hs_b) + __high2float(hs_b);

        // O += P V
#pragma unroll
        for (int kk = 0; kk < 4; kk++) {
#pragma unroll
            for (int nb = 0; nb < 4; nb++) {
                uint32_t vf[4];
                ldsm4t(vf, &V_[(kk * 16 + (l % 8) + 8 * ((l >> 3) & 1)) * 72 + nb * 16 + 8 * (l >> 4)]);
                mma16816(o[2 * nb + 0], pa[kk], vf[0], vf[1]);
                mma16816(o[2 * nb + 1], pa[kk], vf[2], vf[3]);
            }
        }
    }

    // lane-quad reduce of l (partial sums live on 4 lanes per row)
    l_a += __shfl_xor_sync(0xffffffffu, l_a, 1);
    l_a += __shfl_xor_sync(0xffffffffu, l_a, 2);
    l_b += __shfl_xor_sync(0xffffffffu, l_b, 1);
    l_b += __shfl_xor_sync(0xffffffffu, l_b, 2);

    float inv_a = (l_a > 0.f) ? 1.f / l_a : 0.f;
    float inv_b = (l_b > 0.f) ? 1.f / l_b : 0.f;
    int rowa = (b * SEQ + q0 + ra_local) * DMODEL + h * DH;
    int rowb = rowa + 8 * DMODEL;
#pragma unroll
    for (int n8 = 0; n8 < 8; n8++) {
        int c = n8 * 8 + t2;
        *reinterpret_cast<__half2*>(&g_ctx[rowa + c]) =
            __floats2half2_rn(o[n8][0] * inv_a, o[n8][1] * inv_a);
        *reinterpret_cast<__half2*>(&g_ctx[rowb + c]) =
            __floats2half2_rn(o[n8][2] * inv_b, o[n8][3] * inv_b);
    }
}

// ---------------------------------------------------------------- launch

extern "C" void kernel_launch(void* const* d_in, const int* in_sizes, int n_in,
                              void* d_out, int out_size)
{
    const float* Q    = (const float*)d_in[0];
    const float* K    = (const float*)d_in[1];
    const float* V    = (const float*)d_in[2];
    const int*   mask = (const int*)  d_in[3];
    const float* Wq   = (const float*)d_in[4];
    const float* bq   = (const float*)d_in[5];
    const float* Wk   = (const float*)d_in[6];
    const float* bk   = (const float*)d_in[7];
    const float* Wv   = (const float*)d_in[8];
    const float* bv   = (const float*)d_in[9];
    const float* Wo   = (const float*)d_in[10];
    const float* bo   = (const float*)d_in[11];
    float* out = (float*)d_out;

    __half *xq, *xk, *xv, *wq, *wk, *wv, *wo, *ctx;
    cudaGetSymbolAddress((void**)&xq, g_xq);
    cudaGetSymbolAddress((void**)&xk, g_xk);
    cudaGetSymbolAddress((void**)&xv, g_xv);
    cudaGetSymbolAddress((void**)&wq, g_wq);
    cudaGetSymbolAddress((void**)&wk, g_wk);
    cudaGetSymbolAddress((void**)&wv, g_wv);
    cudaGetSymbolAddress((void**)&wo, g_wo);
    cudaGetSymbolAddress((void**)&ctx, g_ctx);

    prep_kernel<<<6656, 256>>>(Q, K, V, Wq, Wk, Wv, Wo);

    qkv_kernel<<<dim3(ROWS / 128, DMODEL / 128, 4), 256>>>(
        mask, xq, xk, xv, wq, wk, wv, bq, bk, bv);

    attn_kernel<<<dim3(SEQ / 128, NH, BATCH), 256>>>();

    oproj_kernel<<<dim3(ROWS / 128, DMODEL / 128), 256>>>(ctx, wo, bo, out);
}

// round 15
// speedup vs baseline: 1.0479x; 1.0479x over previous
#include <cuda_runtime.h>
#include <cuda_fp16.h>
#include <cstdint>
#include <cfloat>

#define DEVI __device__ __forceinline__

static constexpr int BATCH  = 4;
static constexpr int SEQ    = 2048;
static constexpr int DMODEL = 512;
static constexpr int NH     = 8;
static constexpr int DH     = 64;
static constexpr int ROWS   = BATCH * SEQ;          // 8192

// Scratch (allocation-free rule: device globals)
__device__ __align__(16) __half   g_xq[ROWS * DMODEL];
__device__ __align__(16) __half   g_xk[ROWS * DMODEL];
__device__ __align__(16) __half   g_xv[ROWS * DMODEL];
__device__ __align__(16) __half   g_wq[DMODEL * DMODEL];
__device__ __align__(16) __half   g_wk[DMODEL * DMODEL];
__device__ __align__(16) __half   g_wv[DMODEL * DMODEL];
__device__ __align__(16) __half   g_wo[DMODEL * DMODEL];
__device__ __align__(16) __half   g_q[BATCH * NH * SEQ * DH];
__device__ __align__(16) __half   g_k[BATCH * NH * SEQ * DH];
__device__ __align__(16) __half   g_v[BATCH * NH * SEQ * DH];
__device__ __align__(16) __half   g_ctx[ROWS * DMODEL];
__device__            unsigned    g_maskp[BATCH * SEQ * (SEQ / 32)];

// ---------------------------------------------------------------- helpers

DEVI uint32_t smaddr(const void* p) { return (uint32_t)__cvta_generic_to_shared(p); }

DEVI void ldsm4(uint32_t r[4], const void* p) {
    uint32_t a = smaddr(p);
    asm volatile("ldmatrix.sync.aligned.m8n8.x4.shared.b16 {%0,%1,%2,%3}, [%4];"
                 : "=r"(r[0]), "=r"(r[1]), "=r"(r[2]), "=r"(r[3]) : "r"(a));
}
DEVI void ldsm4t(uint32_t r[4], const void* p) {
    uint32_t a = smaddr(p);
    asm volatile("ldmatrix.sync.aligned.m8n8.x4.trans.shared.b16 {%0,%1,%2,%3}, [%4];"
                 : "=r"(r[0]), "=r"(r[1]), "=r"(r[2]), "=r"(r[3]) : "r"(a));
}

DEVI void mma16816(float c[4], const uint32_t a[4], uint32_t b0, uint32_t b1) {
    asm volatile(
        "mma.sync.aligned.m16n8k16.row.col.f32.f16.f16.f32 "
        "{%0,%1,%2,%3}, {%4,%5,%6,%7}, {%8,%9}, {%0,%1,%2,%3};"
        : "+f"(c[0]), "+f"(c[1]), "+f"(c[2]), "+f"(c[3])
        : "r"(a[0]), "r"(a[1]), "r"(a[2]), "r"(a[3]), "r"(b0), "r"(b1));
}

DEVI uint32_t f2h2(float x, float y) {
    __half2 h = __floats2half2_rn(x, y);
    return *reinterpret_cast<uint32_t*>(&h);
}

DEVI float ex2(float x) {
    float y;
    asm("ex2.approx.ftz.f32 %0, %1;" : "=f"(y) : "f"(x));
    return y;
}

DEVI void cpa16(void* dst, const void* src) {
    asm volatile("cp.async.cg.shared.global [%0], [%1], 16;" :: "r"(smaddr(dst)), "l"(src));
}
DEVI void cpa4(void* dst, const void* src) {
    asm volatile("cp.async.ca.shared.global [%0], [%1], 4;" :: "r"(smaddr(dst)), "l"(src));
}
DEVI void cpcommit() { asm volatile("cp.async.commit_group;"); }
DEVI void cpwait0()  { asm volatile("cp.async.wait_group 0;"); }

// ---------------------------------------------------------------- prep: fp32->fp16 converts ONLY
// (mask packing lives in the qkv launch, where its DRAM traffic overlaps
//  qkv's tensor-bound compute — the round-13 measured win)

__global__ __launch_bounds__(256) void prep_kernel(
    const float* __restrict__ Q, const float* __restrict__ K, const float* __restrict__ V,
    const float* __restrict__ Wq, const float* __restrict__ Wk,
    const float* __restrict__ Wv, const float* __restrict__ Wo)
{
    int blk = blockIdx.x;
    const float* src; __half* dst; int off;
    if      (blk < 2048) { src = Q;  dst = g_xq; off = blk; }
    else if (blk < 4096) { src = K;  dst = g_xk; off = blk - 2048; }
    else if (blk < 6144) { src = V;  dst = g_xv; off = blk - 4096; }
    else if (blk < 6272) { src = Wq; dst = g_wq; off = blk - 6144; }
    else if (blk < 6400) { src = Wk; dst = g_wk; off = blk - 6272; }
    else if (blk < 6528) { src = Wv; dst = g_wv; off = blk - 6400; }
    else                 { src = Wo; dst = g_wo; off = blk - 6528; }
    int base = off * 2048 + threadIdx.x * 8;
    float4 v0 = *reinterpret_cast<const float4*>(&src[base]);
    float4 v1 = *reinterpret_cast<const float4*>(&src[base + 4]);
    __half2 h[4] = { __floats2half2_rn(v0.x, v0.y), __floats2half2_rn(v0.z, v0.w),
                     __floats2half2_rn(v1.x, v1.y), __floats2half2_rn(v1.z, v1.w) };
    *reinterpret_cast<uint4*>(&dst[base]) = *reinterpret_cast<uint4*>(h);
}

// ---------------------------------------------------------------- QKV GEMM + mask pack (z = 0..2 gemm, z = 3 mask)
// C[8192,512] = X * W + bias -> fp16 scattered to [b,h,s,d]. z==0 folds 0.125*log2e.
// CTA tile 128x128, BK=32, 256 threads, 2-stage cp.async double buffer.
// z==3 slice (256 CTAs): pack mask int32 -> bits; DRAM-bound work overlapping
// the tensor-bound GEMM slices in the same launch.

__global__ __launch_bounds__(256) void qkv_kernel(
    const int* __restrict__ mask,
    const __half* __restrict__ A0, const __half* __restrict__ A1, const __half* __restrict__ A2,
    const __half* __restrict__ W0, const __half* __restrict__ W1, const __half* __restrict__ W2,
    const float* __restrict__ b0p, const float* __restrict__ b1p, const float* __restrict__ b2p)
{
    __shared__ __half sA[2][128 * 40];
    __shared__ __half sB[2][32 * 136];

    int tid = threadIdx.x, l = tid & 31, w = tid >> 5;
    int z = blockIdx.z;

    if (z == 3) {           // ---- mask packing slice: 256 CTAs x 2048 words
        int cta = blockIdx.x * 4 + blockIdx.y;          // 0..255
#pragma unroll
        for (int i = 0; i < 8; i++) {
            int wi = cta * 2048 + i * 256 + tid;
            const int4* p = reinterpret_cast<const int4*>(mask) + wi * 8;
            unsigned bits = 0;
#pragma unroll
            for (int j = 0; j < 8; j++) {
                int4 v = p[j];
                bits |= (v.x != 0 ? 1u : 0u) << (j * 4 + 0);
                bits |= (v.y != 0 ? 1u : 0u) << (j * 4 + 1);
                bits |= (v.z != 0 ? 1u : 0u) << (j * 4 + 2);
                bits |= (v.w != 0 ? 1u : 0u) << (j * 4 + 3);
            }
            g_maskp[wi] = bits;
        }
        return;
    }

    int wm = w >> 1, wn = w & 1;
    int m0 = blockIdx.x * 128, n0 = blockIdx.y * 128;
    const __half* A = (z == 0) ? A0 : (z == 1) ? A1 : A2;
    const __half* W = (z == 0) ? W0 : (z == 1) ? W1 : W2;
    const float* bias = (z == 0) ? b0p : (z == 1) ? b1p : b2p;

    float o[2][8][4];
#pragma unroll
    for (int mb = 0; mb < 2; mb++)
#pragma unroll
        for (int i = 0; i < 8; i++)
#pragma unroll
            for (int j = 0; j < 4; j++) o[mb][i][j] = 0.f;

    {  // prefetch stage 0
#pragma unroll
        for (int i = 0; i < 2; i++) {
            int c = tid + i * 256; int r = c >> 2, cc = (c & 3) * 8;
            cpa16(&sA[0][r * 40 + cc], &A[(m0 + r) * 512 + cc]);
        }
#pragma unroll
        for (int i = 0; i < 2; i++) {
            int c = tid + i * 256; int r = c >> 4, cc = (c & 15) * 8;
            cpa16(&sB[0][r * 136 + cc], &W[r * 512 + n0 + cc]);
        }
        cpcommit();
    }

    for (int t = 0; t < 16; t++) {
        cpwait0();
        __syncthreads();
        if (t < 15) {
            int buf = (t + 1) & 1, t1 = t + 1;
#pragma unroll
            for (int i = 0; i < 2; i++) {
                int c = tid + i * 256; int r = c >> 2, cc = (c & 3) * 8;
                cpa16(&sA[buf][r * 40 + cc], &A[(m0 + r) * 512 + t1 * 32 + cc]);
            }
#pragma unroll
            for (int i = 0; i < 2; i++) {
                int c = tid + i * 256; int r = c >> 4, cc = (c & 15) * 8;
                cpa16(&sB[buf][r * 136 + cc], &W[(t1 * 32 + r) * 512 + n0 + cc]);
            }
            cpcommit();
        }
        const __half* a_ = sA[t & 1];
        const __half* b_ = sB[t & 1];
#pragma unroll
        for (int kk = 0; kk < 2; kk++) {
            uint32_t af[2][4];
#pragma unroll
            for (int mb = 0; mb < 2; mb++)
                ldsm4(af[mb], &a_[(wm * 32 + mb * 16 + (l % 16)) * 40 + kk * 16 + 8 * (l / 16)]);
#pragma unroll
            for (int nb = 0; nb < 4; nb++) {
                uint32_t bf[4];
                ldsm4t(bf, &b_[(kk * 16 + (l % 8) + 8 * ((l >> 3) & 1)) * 136 + wn * 64 + nb * 16 + 8 * (l >> 4)]);
#pragma unroll
                for (int mb = 0; mb < 2; mb++) {
                    mma16816(o[mb][2 * nb + 0], af[mb], bf[0], bf[1]);
                    mma16816(o[mb][2 * nb + 1], af[mb], bf[2], bf[3]);
                }
            }
        }
    }

    int t2 = (l & 3) * 2;
    __half* dst = (z == 0) ? g_q : (z == 1) ? g_k : g_v;
    float s = (z == 0) ? 0.1803368801111204f : 1.f;   // 1/sqrt(64)*log2(e) folded into q
    int h = (n0 + wn * 64) >> 6;
#pragma unroll
    for (int mb = 0; mb < 2; mb++) {
        int ra = m0 + wm * 32 + mb * 16 + (l >> 2);
        int rb = ra + 8;
        int ba = ra >> 11, sa = ra & 2047;
        int bb = rb >> 11, sb = rb & 2047;
#pragma unroll
        for (int n8 = 0; n8 < 8; n8++) {
            int c = n0 + wn * 64 + n8 * 8 + t2;
            int d = c & 63;
            float c0 = bias[c], c1 = bias[c + 1];
            int ia = (((ba << 3) + h) * SEQ + sa) * DH + d;
            int ib = (((bb << 3) + h) * SEQ + sb) * DH + d;
            *reinterpret_cast<__half2*>(&dst[ia]) =
                __floats2half2_rn((o[mb][n8][0] + c0) * s, (o[mb][n8][1] + c1) * s);
            *reinterpret_cast<__half2*>(&dst[ib]) =
                __floats2half2_rn((o[mb][n8][2] + c0) * s, (o[mb][n8][3] + c1) * s);
        }
    }
}

// ---------------------------------------------------------------- output projection
// out = ctx[8192,512](fp16) * Wo + bo -> fp32

__global__ __launch_bounds__(256) void oproj_kernel(
    const __half* __restrict__ A, const __half* __restrict__ W,
    const float* __restrict__ bias, float* __restrict__ outf)
{
    __shared__ __half sA[2][128 * 40];
    __shared__ __half sB[2][32 * 136];

    int tid = threadIdx.x, l = tid & 31, w = tid >> 5;
    int wm = w >> 1, wn = w & 1;
    int m0 = blockIdx.x * 128, n0 = blockIdx.y * 128;

    float o[2][8][4];
#pragma unroll
    for (int mb = 0; mb < 2; mb++)
#pragma unroll
        for (int i = 0; i < 8; i++)
#pragma unroll
            for (int j = 0; j < 4; j++) o[mb][i][j] = 0.f;

    {
#pragma unroll
        for (int i = 0; i < 2; i++) {
            int c = tid + i * 256; int r = c >> 2, cc = (c & 3) * 8;
            cpa16(&sA[0][r * 40 + cc], &A[(m0 + r) * 512 + cc]);
        }
#pragma unroll
        for (int i = 0; i < 2; i++) {
            int c = tid + i * 256; int r = c >> 4, cc = (c & 15) * 8;
            cpa16(&sB[0][r * 136 + cc], &W[r * 512 + n0 + cc]);
        }
        cpcommit();
    }

    for (int t = 0; t < 16; t++) {
        cpwait0();
        __syncthreads();
        if (t < 15) {
            int buf = (t + 1) & 1, t1 = t + 1;
#pragma unroll
            for (int i = 0; i < 2; i++) {
                int c = tid + i * 256; int r = c >> 2, cc = (c & 3) * 8;
                cpa16(&sA[buf][r * 40 + cc], &A[(m0 + r) * 512 + t1 * 32 + cc]);
            }
#pragma unroll
            for (int i = 0; i < 2; i++) {
                int c = tid + i * 256; int r = c >> 4, cc = (c & 15) * 8;
                cpa16(&sB[buf][r * 136 + cc], &W[(t1 * 32 + r) * 512 + n0 + cc]);
            }
            cpcommit();
        }
        const __half* a_ = sA[t & 1];
        const __half* b_ = sB[t & 1];
#pragma unroll
        for (int kk = 0; kk < 2; kk++) {
            uint32_t af[2][4];
#pragma unroll
            for (int mb = 0; mb < 2; mb++)
                ldsm4(af[mb], &a_[(wm * 32 + mb * 16 + (l % 16)) * 40 + kk * 16 + 8 * (l / 16)]);
#pragma unroll
            for (int nb = 0; nb < 4; nb++) {
                uint32_t bf[4];
                ldsm4t(bf, &b_[(kk * 16 + (l % 8) + 8 * ((l >> 3) & 1)) * 136 + wn * 64 + nb * 16 + 8 * (l >> 4)]);
#pragma unroll
                for (int mb = 0; mb < 2; mb++) {
                    mma16816(o[mb][2 * nb + 0], af[mb], bf[0], bf[1]);
                    mma16816(o[mb][2 * nb + 1], af[mb], bf[2], bf[3]);
                }
            }
        }
    }

    int t2 = (l & 3) * 2;
#pragma unroll
    for (int mb = 0; mb < 2; mb++) {
        int ra = m0 + wm * 32 + mb * 16 + (l >> 2);
        int rb = ra + 8;
#pragma unroll
        for (int n8 = 0; n8 < 8; n8++) {
            int c = n0 + wn * 64 + n8 * 8 + t2;
            float c0 = bias[c], c1 = bias[c + 1];
            *reinterpret_cast<float2*>(&outf[ra * 512 + c]) =
                make_float2(o[mb][n8][0] + c0, o[mb][n8][1] + c1);
            *reinterpret_cast<float2*>(&outf[rb * 512 + c]) =
                make_float2(o[mb][n8][2] + c0, o[mb][n8][3] + c1);
        }
    }
}

// ---------------------------------------------------------------- flash attention
// CTA: 128 q rows of one (b,h). 8 warps x 16 rows. BK=64 keys/iter, 32 iters.
// Constant-shift softmax (scores bounded by construction; p/l normalization
// makes the shift exact), fp32 scalar exp path — measured optimal (R12/R14
// falsified both fp16 softmax variants). Smem arena [K0|V0|K1|V1]; Q staging
// aliases [K1|V1].

__global__ __launch_bounds__(256) void attn_kernel() {
    __shared__ __align__(16) __half sKV[4 * 64 * 72];   // 4608 halves per buffer
    __shared__ unsigned sM[2][256];

    int tid = threadIdx.x, l = tid & 31, w = tid >> 5;
    int q0 = blockIdx.x * 128, h = blockIdx.y, b = blockIdx.z;
    int bh = b * NH + h;
    const __half* gq = &g_q[(bh * SEQ + q0) * DH];

    __half* sQ = &sKV[2 * 4608];                        // aliases [K1|V1]

#pragma unroll
    for (int i = 0; i < 4; i++) {
        int e = tid + i * 256;
        int r = e >> 3, c = (e & 7) * 8;
        *reinterpret_cast<uint4*>(&sQ[r * 72 + c]) =
            *reinterpret_cast<const uint4*>(&gq[r * 64 + c]);
    }

    {   // prefetch stage 0 (K0/V0 — disjoint from sQ alias)
        const __half* gk = &g_k[(bh * SEQ) * DH];
        const __half* gv = &g_v[(bh * SEQ) * DH];
#pragma unroll
        for (int i = 0; i < 2; i++) {
            int c = tid + i * 256; int r = c >> 3, cc = (c & 7) * 8;
            cpa16(&sKV[0 * 4608 + r * 72 + cc], &gk[r * 64 + cc]);
            cpa16(&sKV[1 * 4608 + r * 72 + cc], &gv[r * 64 + cc]);
        }
        cpa4(&sM[0][tid], &g_maskp[(b * SEQ + q0 + (tid >> 1)) * (SEQ / 32) + (tid & 1)]);
        cpcommit();
    }
    __syncthreads();   // sQ visible

    uint32_t qa[4][4];
#pragma unroll
    for (int kk = 0; kk < 4; kk++)
        ldsm4(qa[kk], &sQ[(w * 16 + (l % 16)) * 72 + kk * 16 + 8 * (l / 16)]);

    __syncthreads();   // all threads done reading sQ before anyone writes buf1

    float o[8][4];
#pragma unroll
    for (int i = 0; i < 8; i++)
#pragma unroll
        for (int j = 0; j < 4; j++) o[i][j] = 0.f;
    float l_a = 0.f, l_b = 0.f;

    int ra_local = w * 16 + (l >> 2);
    int t2 = (l & 3) * 2;

    for (int kt = 0; kt < 32; kt++) {
        cpwait0();
        __syncthreads();
        if (kt < 31) {
            int buf = (kt + 1) & 1;
            const __half* gk = &g_k[(bh * SEQ + (kt + 1) * 64) * DH];
            const __half* gv = &g_v[(bh * SEQ + (kt + 1) * 64) * DH];
#pragma unroll
            for (int i = 0; i < 2; i++) {
                int c = tid + i * 256; int r = c >> 3, cc = (c & 7) * 8;
                cpa16(&sKV[(2 * buf + 0) * 4608 + r * 72 + cc], &gk[r * 64 + cc]);
                cpa16(&sKV[(2 * buf + 1) * 4608 + r * 72 + cc], &gv[r * 64 + cc]);
            }
            cpa4(&sM[buf][tid],
                 &g_maskp[(b * SEQ + q0 + (tid >> 1)) * (SEQ / 32) + (kt + 1) * 2 + (tid & 1)]);
            cpcommit();
        }
        const __half*   K_ = &sKV[(2 * (kt & 1) + 0) * 4608];
        const __half*   V_ = &sKV[(2 * (kt & 1) + 1) * 4608];
        const unsigned* M_ = sM[kt & 1];

        // S = Q K^T  (already includes 0.125*log2e via q)
        float sc[8][4];
#pragma unroll
        for (int i = 0; i < 8; i++)
#pragma unroll
            for (int j = 0; j < 4; j++) sc[i][j] = 0.f;
#pragma unroll
        for (int kk = 0; kk < 4; kk++) {
#pragma unroll
            for (int nb = 0; nb < 4; nb++) {
                uint32_t kf[4];
                ldsm4(kf, &K_[(nb * 16 + (l % 8) + 8 * (l >> 4)) * 72 + kk * 16 + 8 * ((l >> 3) & 1)]);
                mma16816(sc[2 * nb + 0], qa[kk], kf[0], kf[1]);
                mma16816(sc[2 * nb + 1], qa[kk], kf[2], kf[3]);
            }
        }

        // constant-shift softmax: p = mask ? exp2(s) : 0; accumulate l
        unsigned ma0 = M_[ra_local * 2 + 0],       ma1 = M_[ra_local * 2 + 1];
        unsigned mb0 = M_[(ra_local + 8) * 2 + 0], mb1 = M_[(ra_local + 8) * 2 + 1];

        float sum_a = 0.f, sum_b = 0.f;
#pragma unroll
        for (int n8 = 0; n8 < 8; n8++) {
#pragma unroll
            for (int j = 0; j < 2; j++) {
                int col = n8 * 8 + t2 + j;
                unsigned wa = (col < 32) ? ma0 : ma1;
                unsigned wb = (col < 32) ? mb0 : mb1;
                float pa = ex2(sc[n8][j]);
                float pb = ex2(sc[n8][2 + j]);
                pa = ((wa >> (col & 31)) & 1) ? pa : 0.f;
                pb = ((wb >> (col & 31)) & 1) ? pb : 0.f;
                sc[n8][j] = pa;  sc[n8][2 + j] = pb;
                sum_a += pa;  sum_b += pb;
            }
        }
        l_a += sum_a;
        l_b += sum_b;

        uint32_t pa[4][4];
#pragma unroll
        for (int kk = 0; kk < 4; kk++) {
            pa[kk][0] = f2h2(sc[2 * kk][0], sc[2 * kk][1]);
            pa[kk][1] = f2h2(sc[2 * kk][2], sc[2 * kk][3]);
            pa[kk][2] = f2h2(sc[2 * kk + 1][0], sc[2 * kk + 1][1]);
            pa[kk][3] = f2h2(sc[2 * kk + 1][2], sc[2 * kk + 1][3]);
        }

#pragma unroll
        for (int kk = 0; kk < 4; kk++) {
#pragma unroll
            for (int nb = 0; nb < 4; nb++) {
                uint32_t vf[4];
                ldsm4t(vf, &V_[(kk * 16 + (l % 8) + 8 * ((l >> 3) & 1)) * 72 + nb * 16 + 8 * (l >> 4)]);
                mma16816(o[2 * nb + 0], pa[kk], vf[0], vf[1]);
                mma16816(o[2 * nb + 1], pa[kk], vf[2], vf[3]);
            }
        }
    }

    // lane-quad reduce of l (partial sums live on 4 lanes per row)
    l_a += __shfl_xor_sync(0xffffffffu, l_a, 1);
    l_a += __shfl_xor_sync(0xffffffffu, l_a, 2);
    l_b += __shfl_xor_sync(0xffffffffu, l_b, 1);
    l_b += __shfl_xor_sync(0xffffffffu, l_b, 2);

    float inv_a = (l_a > 0.f) ? 1.f / l_a : 0.f;
    float inv_b = (l_b > 0.f) ? 1.f / l_b : 0.f;
    int rowa = (b * SEQ + q0 + ra_local) * DMODEL + h * DH;
    int rowb = rowa + 8 * DMODEL;
#pragma unroll
    for (int n8 = 0; n8 < 8; n8++) {
        int c = n8 * 8 + t2;
        *reinterpret_cast<__half2*>(&g_ctx[rowa + c]) =
            __floats2half2_rn(o[n8][0] * inv_a, o[n8][1] * inv_a);
        *reinterpret_cast<__half2*>(&g_ctx[rowb + c]) =
            __floats2half2_rn(o[n8][2] * inv_b, o[n8][3] * inv_b);
    }
}

// ---------------------------------------------------------------- launch

extern "C" void kernel_launch(void* const* d_in, const int* in_sizes, int n_in,
                              void* d_out, int out_size)
{
    const float* Q    = (const float*)d_in[0];
    const float* K    = (const float*)d_in[1];
    const float* V    = (const float*)d_in[2];
    const int*   mask = (const int*)  d_in[3];
    const float* Wq   = (const float*)d_in[4];
    const float* bq   = (const float*)d_in[5];
    const float* Wk   = (const float*)d_in[6];
    const float* bk   = (const float*)d_in[7];
    const float* Wv   = (const float*)d_in[8];
    const float* bv   = (const float*)d_in[9];
    const float* Wo   = (const float*)d_in[10];
    const float* bo   = (const float*)d_in[11];
    float* out = (float*)d_out;

    __half *xq, *xk, *xv, *wq, *wk, *wv, *wo, *ctx;
    cudaGetSymbolAddress((void**)&xq, g_xq);
    cudaGetSymbolAddress((void**)&xk, g_xk);
    cudaGetSymbolAddress((void**)&xv, g_xv);
    cudaGetSymbolAddress((void**)&wq, g_wq);
    cudaGetSymbolAddress((void**)&wk, g_wk);
    cudaGetSymbolAddress((void**)&wv, g_wv);
    cudaGetSymbolAddress((void**)&wo, g_wo);
    cudaGetSymbolAddress((void**)&ctx, g_ctx);

    prep_kernel<<<6656, 256>>>(Q, K, V, Wq, Wk, Wv, Wo);

    qkv_kernel<<<dim3(ROWS / 128, DMODEL / 128, 4), 256>>>(
        mask, xq, xk, xv, wq, wk, wv, bq, bk, bv);

    attn_kernel<<<dim3(SEQ / 128, NH, BATCH), 256>>>();

    oproj_kernel<<<dim3(ROWS / 128, DMODEL / 128), 256>>>(ctx, wo, bo, out);
}

// round 16
// speedup vs baseline: 1.1050x; 1.0545x over previous
#include <cuda_runtime.h>
#include <cuda_fp16.h>
#include <cstdint>
#include <cfloat>

#define DEVI __device__ __forceinline__

static constexpr int BATCH  = 4;
static constexpr int SEQ    = 2048;
static constexpr int DMODEL = 512;
static constexpr int NH     = 8;
static constexpr int DH     = 64;
static constexpr int ROWS   = BATCH * SEQ;          // 8192

// Scratch (allocation-free rule: device globals)
__device__ __align__(16) __half   g_xq[ROWS * DMODEL];
__device__ __align__(16) __half   g_xk[ROWS * DMODEL];
__device__ __align__(16) __half   g_xv[ROWS * DMODEL];
__device__ __align__(16) __half   g_wq[DMODEL * DMODEL];
__device__ __align__(16) __half   g_wk[DMODEL * DMODEL];
__device__ __align__(16) __half   g_wv[DMODEL * DMODEL];
__device__ __align__(16) __half   g_wo[DMODEL * DMODEL];
__device__ __align__(16) __half   g_q[BATCH * NH * SEQ * DH];
__device__ __align__(16) __half   g_k[BATCH * NH * SEQ * DH];
__device__ __align__(16) __half   g_v[BATCH * NH * SEQ * DH];
__device__ __align__(16) __half   g_ctx[ROWS * DMODEL];
__device__            unsigned    g_maskp[BATCH * SEQ * (SEQ / 32)];

// ---------------------------------------------------------------- helpers

DEVI uint32_t smaddr(const void* p) { return (uint32_t)__cvta_generic_to_shared(p); }

DEVI void ldsm4(uint32_t r[4], const void* p) {
    uint32_t a = smaddr(p);
    asm volatile("ldmatrix.sync.aligned.m8n8.x4.shared.b16 {%0,%1,%2,%3}, [%4];"
                 : "=r"(r[0]), "=r"(r[1]), "=r"(r[2]), "=r"(r[3]) : "r"(a));
}
DEVI void ldsm4t(uint32_t r[4], const void* p) {
    uint32_t a = smaddr(p);
    asm volatile("ldmatrix.sync.aligned.m8n8.x4.trans.shared.b16 {%0,%1,%2,%3}, [%4];"
                 : "=r"(r[0]), "=r"(r[1]), "=r"(r[2]), "=r"(r[3]) : "r"(a));
}

DEVI void mma16816(float c[4], const uint32_t a[4], uint32_t b0, uint32_t b1) {
    asm volatile(
        "mma.sync.aligned.m16n8k16.row.col.f32.f16.f16.f32 "
        "{%0,%1,%2,%3}, {%4,%5,%6,%7}, {%8,%9}, {%0,%1,%2,%3};"
        : "+f"(c[0]), "+f"(c[1]), "+f"(c[2]), "+f"(c[3])
        : "r"(a[0]), "r"(a[1]), "r"(a[2]), "r"(a[3]), "r"(b0), "r"(b1));
}

DEVI uint32_t f2h2(float x, float y) {
    __half2 h = __floats2half2_rn(x, y);
    return *reinterpret_cast<uint32_t*>(&h);
}

DEVI float ex2(float x) {
    float y;
    asm("ex2.approx.ftz.f32 %0, %1;" : "=f"(y) : "f"(x));
    return y;
}

DEVI void cpa16(void* dst, const void* src) {
    asm volatile("cp.async.cg.shared.global [%0], [%1], 16;" :: "r"(smaddr(dst)), "l"(src));
}
DEVI void cpa4(void* dst, const void* src) {
    asm volatile("cp.async.ca.shared.global [%0], [%1], 4;" :: "r"(smaddr(dst)), "l"(src));
}
DEVI void cpcommit() { asm volatile("cp.async.commit_group;"); }
DEVI void cpwait0()  { asm volatile("cp.async.wait_group 0;"); }

// ---------------------------------------------------------------- prep: fp32->fp16 converts ONLY

__global__ __launch_bounds__(256) void prep_kernel(
    const float* __restrict__ Q, const float* __restrict__ K, const float* __restrict__ V,
    const float* __restrict__ Wq, const float* __restrict__ Wk,
    const float* __restrict__ Wv, const float* __restrict__ Wo)
{
    int blk = blockIdx.x;
    const float* src; __half* dst; int off;
    if      (blk < 2048) { src = Q;  dst = g_xq; off = blk; }
    else if (blk < 4096) { src = K;  dst = g_xk; off = blk - 2048; }
    else if (blk < 6144) { src = V;  dst = g_xv; off = blk - 4096; }
    else if (blk < 6272) { src = Wq; dst = g_wq; off = blk - 6144; }
    else if (blk < 6400) { src = Wk; dst = g_wk; off = blk - 6272; }
    else if (blk < 6528) { src = Wv; dst = g_wv; off = blk - 6400; }
    else                 { src = Wo; dst = g_wo; off = blk - 6528; }
    int base = off * 2048 + threadIdx.x * 8;
    float4 v0 = *reinterpret_cast<const float4*>(&src[base]);
    float4 v1 = *reinterpret_cast<const float4*>(&src[base + 4]);
    __half2 h[4] = { __floats2half2_rn(v0.x, v0.y), __floats2half2_rn(v0.z, v0.w),
                     __floats2half2_rn(v1.x, v1.y), __floats2half2_rn(v1.z, v1.w) };
    *reinterpret_cast<uint4*>(&dst[base]) = *reinterpret_cast<uint4*>(h);
}

// ---------------------------------------------------------------- QKV GEMM + mask pack (z = 0..2 gemm, z = 3 mask)
// (unchanged from the verified 240.4us best)

__global__ __launch_bounds__(256) void qkv_kernel(
    const int* __restrict__ mask,
    const __half* __restrict__ A0, const __half* __restrict__ A1, const __half* __restrict__ A2,
    const __half* __restrict__ W0, const __half* __restrict__ W1, const __half* __restrict__ W2,
    const float* __restrict__ b0p, const float* __restrict__ b1p, const float* __restrict__ b2p)
{
    __shared__ __half sA[2][128 * 40];
    __shared__ __half sB[2][32 * 136];

    int tid = threadIdx.x, l = tid & 31, w = tid >> 5;
    int z = blockIdx.z;

    if (z == 3) {           // ---- mask packing slice: 256 CTAs x 2048 words
        int cta = blockIdx.x * 4 + blockIdx.y;          // 0..255
#pragma unroll
        for (int i = 0; i < 8; i++) {
            int wi = cta * 2048 + i * 256 + tid;
            const int4* p = reinterpret_cast<const int4*>(mask) + wi * 8;
            unsigned bits = 0;
#pragma unroll
            for (int j = 0; j < 8; j++) {
                int4 v = p[j];
                bits |= (v.x != 0 ? 1u : 0u) << (j * 4 + 0);
                bits |= (v.y != 0 ? 1u : 0u) << (j * 4 + 1);
                bits |= (v.z != 0 ? 1u : 0u) << (j * 4 + 2);
                bits |= (v.w != 0 ? 1u : 0u) << (j * 4 + 3);
            }
            g_maskp[wi] = bits;
        }
        return;
    }

    int wm = w >> 1, wn = w & 1;
    int m0 = blockIdx.x * 128, n0 = blockIdx.y * 128;
    const __half* A = (z == 0) ? A0 : (z == 1) ? A1 : A2;
    const __half* W = (z == 0) ? W0 : (z == 1) ? W1 : W2;
    const float* bias = (z == 0) ? b0p : (z == 1) ? b1p : b2p;

    float o[2][8][4];
#pragma unroll
    for (int mb = 0; mb < 2; mb++)
#pragma unroll
        for (int i = 0; i < 8; i++)
#pragma unroll
            for (int j = 0; j < 4; j++) o[mb][i][j] = 0.f;

    {  // prefetch stage 0
#pragma unroll
        for (int i = 0; i < 2; i++) {
            int c = tid + i * 256; int r = c >> 2, cc = (c & 3) * 8;
            cpa16(&sA[0][r * 40 + cc], &A[(m0 + r) * 512 + cc]);
        }
#pragma unroll
        for (int i = 0; i < 2; i++) {
            int c = tid + i * 256; int r = c >> 4, cc = (c & 15) * 8;
            cpa16(&sB[0][r * 136 + cc], &W[r * 512 + n0 + cc]);
        }
        cpcommit();
    }

    for (int t = 0; t < 16; t++) {
        cpwait0();
        __syncthreads();
        if (t < 15) {
            int buf = (t + 1) & 1, t1 = t + 1;
#pragma unroll
            for (int i = 0; i < 2; i++) {
                int c = tid + i * 256; int r = c >> 2, cc = (c & 3) * 8;
                cpa16(&sA[buf][r * 40 + cc], &A[(m0 + r) * 512 + t1 * 32 + cc]);
            }
#pragma unroll
            for (int i = 0; i < 2; i++) {
                int c = tid + i * 256; int r = c >> 4, cc = (c & 15) * 8;
                cpa16(&sB[buf][r * 136 + cc], &W[(t1 * 32 + r) * 512 + n0 + cc]);
            }
            cpcommit();
        }
        const __half* a_ = sA[t & 1];
        const __half* b_ = sB[t & 1];
#pragma unroll
        for (int kk = 0; kk < 2; kk++) {
            uint32_t af[2][4];
#pragma unroll
            for (int mb = 0; mb < 2; mb++)
                ldsm4(af[mb], &a_[(wm * 32 + mb * 16 + (l % 16)) * 40 + kk * 16 + 8 * (l / 16)]);
#pragma unroll
            for (int nb = 0; nb < 4; nb++) {
                uint32_t bf[4];
                ldsm4t(bf, &b_[(kk * 16 + (l % 8) + 8 * ((l >> 3) & 1)) * 136 + wn * 64 + nb * 16 + 8 * (l >> 4)]);
#pragma unroll
                for (int mb = 0; mb < 2; mb++) {
                    mma16816(o[mb][2 * nb + 0], af[mb], bf[0], bf[1]);
                    mma16816(o[mb][2 * nb + 1], af[mb], bf[2], bf[3]);
                }
            }
        }
    }

    int t2 = (l & 3) * 2;
    __half* dst = (z == 0) ? g_q : (z == 1) ? g_k : g_v;
    float s = (z == 0) ? 0.1803368801111204f : 1.f;   // 1/sqrt(64)*log2(e) folded into q
    int h = (n0 + wn * 64) >> 6;
#pragma unroll
    for (int mb = 0; mb < 2; mb++) {
        int ra = m0 + wm * 32 + mb * 16 + (l >> 2);
        int rb = ra + 8;
        int ba = ra >> 11, sa = ra & 2047;
        int bb = rb >> 11, sb = rb & 2047;
#pragma unroll
        for (int n8 = 0; n8 < 8; n8++) {
            int c = n0 + wn * 64 + n8 * 8 + t2;
            int d = c & 63;
            float c0 = bias[c], c1 = bias[c + 1];
            int ia = (((ba << 3) + h) * SEQ + sa) * DH + d;
            int ib = (((bb << 3) + h) * SEQ + sb) * DH + d;
            *reinterpret_cast<__half2*>(&dst[ia]) =
                __floats2half2_rn((o[mb][n8][0] + c0) * s, (o[mb][n8][1] + c1) * s);
            *reinterpret_cast<__half2*>(&dst[ib]) =
                __floats2half2_rn((o[mb][n8][2] + c0) * s, (o[mb][n8][3] + c1) * s);
        }
    }
}

// ---------------------------------------------------------------- output projection
// (unchanged from the verified best)

__global__ __launch_bounds__(256) void oproj_kernel(
    const __half* __restrict__ A, const __half* __restrict__ W,
    const float* __restrict__ bias, float* __restrict__ outf)
{
    __shared__ __half sA[2][128 * 40];
    __shared__ __half sB[2][32 * 136];

    int tid = threadIdx.x, l = tid & 31, w = tid >> 5;
    int wm = w >> 1, wn = w & 1;
    int m0 = blockIdx.x * 128, n0 = blockIdx.y * 128;

    float o[2][8][4];
#pragma unroll
    for (int mb = 0; mb < 2; mb++)
#pragma unroll
        for (int i = 0; i < 8; i++)
#pragma unroll
            for (int j = 0; j < 4; j++) o[mb][i][j] = 0.f;

    {
#pragma unroll
        for (int i = 0; i < 2; i++) {
            int c = tid + i * 256; int r = c >> 2, cc = (c & 3) * 8;
            cpa16(&sA[0][r * 40 + cc], &A[(m0 + r) * 512 + cc]);
        }
#pragma unroll
        for (int i = 0; i < 2; i++) {
            int c = tid + i * 256; int r = c >> 4, cc = (c & 15) * 8;
            cpa16(&sB[0][r * 136 + cc], &W[r * 512 + n0 + cc]);
        }
        cpcommit();
    }

    for (int t = 0; t < 16; t++) {
        cpwait0();
        __syncthreads();
        if (t < 15) {
            int buf = (t + 1) & 1, t1 = t + 1;
#pragma unroll
            for (int i = 0; i < 2; i++) {
                int c = tid + i * 256; int r = c >> 2, cc = (c & 3) * 8;
                cpa16(&sA[buf][r * 40 + cc], &A[(m0 + r) * 512 + t1 * 32 + cc]);
            }
#pragma unroll
            for (int i = 0; i < 2; i++) {
                int c = tid + i * 256; int r = c >> 4, cc = (c & 15) * 8;
                cpa16(&sB[buf][r * 136 + cc], &W[(t1 * 32 + r) * 512 + n0 + cc]);
            }
            cpcommit();
        }
        const __half* a_ = sA[t & 1];
        const __half* b_ = sB[t & 1];
#pragma unroll
        for (int kk = 0; kk < 2; kk++) {
            uint32_t af[2][4];
#pragma unroll
            for (int mb = 0; mb < 2; mb++)
                ldsm4(af[mb], &a_[(wm * 32 + mb * 16 + (l % 16)) * 40 + kk * 16 + 8 * (l / 16)]);
#pragma unroll
            for (int nb = 0; nb < 4; nb++) {
                uint32_t bf[4];
                ldsm4t(bf, &b_[(kk * 16 + (l % 8) + 8 * ((l >> 3) & 1)) * 136 + wn * 64 + nb * 16 + 8 * (l >> 4)]);
#pragma unroll
                for (int mb = 0; mb < 2; mb++) {
                    mma16816(o[mb][2 * nb + 0], af[mb], bf[0], bf[1]);
                    mma16816(o[mb][2 * nb + 1], af[mb], bf[2], bf[3]);
                }
            }
        }
    }

    int t2 = (l & 3) * 2;
#pragma unroll
    for (int mb = 0; mb < 2; mb++) {
        int ra = m0 + wm * 32 + mb * 16 + (l >> 2);
        int rb = ra + 8;
#pragma unroll
        for (int n8 = 0; n8 < 8; n8++) {
            int c = n0 + wn * 64 + n8 * 8 + t2;
            float c0 = bias[c], c1 = bias[c + 1];
            *reinterpret_cast<float2*>(&outf[ra * 512 + c]) =
                make_float2(o[mb][n8][0] + c0, o[mb][n8][1] + c1);
            *reinterpret_cast<float2*>(&outf[rb * 512 + c]) =
                make_float2(o[mb][n8][2] + c0, o[mb][n8][3] + c1);
        }
    }
}

// ---------------------------------------------------------------- flash attention
// OCCUPANCY EXPERIMENT: CTA = 64 q rows, 128 threads (4 warps x 16 rows).
// Per-thread register footprint and inner-loop body identical to the 128-row
// version; at ~140 regs/thread this fits 3 CTAs/SM (12 warps) vs 1 CTA
// (8 warps) for the 256-thread version. Grid 1024 CTAs kills the wave tail.
// K/V re-read doubles but stays L2-resident (512KB per (b,h)).
// Constant-shift softmax, fp32 scalar exp (measured optimal, R12/R14).
// Smem arena [K0|V0|K1|V1]; Q staging (4608 halves) aliases [K1].

__global__ __launch_bounds__(128) void attn_kernel() {
    __shared__ __align__(16) __half sKV[4 * 64 * 72];   // 4608 halves per buffer
    __shared__ unsigned sM[2][128];

    int tid = threadIdx.x, l = tid & 31, w = tid >> 5;  // w in 0..3
    int q0 = blockIdx.x * 64, h = blockIdx.y, b = blockIdx.z;
    int bh = b * NH + h;
    const __half* gq = &g_q[(bh * SEQ + q0) * DH];

    __half* sQ = &sKV[2 * 4608];                        // aliases [K1]

    // Q tile: 64x64 halves = 512 uint4, 128 threads x 4
#pragma unroll
    for (int i = 0; i < 4; i++) {
        int e = tid + i * 128;
        int r = e >> 3, c = (e & 7) * 8;
        *reinterpret_cast<uint4*>(&sQ[r * 72 + c]) =
            *reinterpret_cast<const uint4*>(&gq[r * 64 + c]);
    }

    {   // prefetch stage 0 (K0/V0 — disjoint from sQ alias)
        const __half* gk = &g_k[(bh * SEQ) * DH];
        const __half* gv = &g_v[(bh * SEQ) * DH];
#pragma unroll
        for (int i = 0; i < 4; i++) {
            int c = tid + i * 128; int r = c >> 3, cc = (c & 7) * 8;
            cpa16(&sKV[0 * 4608 + r * 72 + cc], &gk[r * 64 + cc]);
            cpa16(&sKV[1 * 4608 + r * 72 + cc], &gv[r * 64 + cc]);
        }
        cpa4(&sM[0][tid], &g_maskp[(b * SEQ + q0 + (tid >> 1)) * (SEQ / 32) + (tid & 1)]);
        cpcommit();
    }
    __syncthreads();   // sQ visible

    uint32_t qa[4][4];
#pragma unroll
    for (int kk = 0; kk < 4; kk++)
        ldsm4(qa[kk], &sQ[(w * 16 + (l % 16)) * 72 + kk * 16 + 8 * (l / 16)]);

    __syncthreads();   // all threads done reading sQ before anyone writes buf1

    float o[8][4];
#pragma unroll
    for (int i = 0; i < 8; i++)
#pragma unroll
        for (int j = 0; j < 4; j++) o[i][j] = 0.f;
    float l_a = 0.f, l_b = 0.f;

    int ra_local = w * 16 + (l >> 2);
    int t2 = (l & 3) * 2;

    for (int kt = 0; kt < 32; kt++) {
        cpwait0();
        __syncthreads();
        if (kt < 31) {
            int buf = (kt + 1) & 1;
            const __half* gk = &g_k[(bh * SEQ + (kt + 1) * 64) * DH];
            const __half* gv = &g_v[(bh * SEQ + (kt + 1) * 64) * DH];
#pragma unroll
            for (int i = 0; i < 4; i++) {
                int c = tid + i * 128; int r = c >> 3, cc = (c & 7) * 8;
                cpa16(&sKV[(2 * buf + 0) * 4608 + r * 72 + cc], &gk[r * 64 + cc]);
                cpa16(&sKV[(2 * buf + 1) * 4608 + r * 72 + cc], &gv[r * 64 + cc]);
            }
            cpa4(&sM[buf][tid],
                 &g_maskp[(b * SEQ + q0 + (tid >> 1)) * (SEQ / 32) + (kt + 1) * 2 + (tid & 1)]);
            cpcommit();
        }
        const __half*   K_ = &sKV[(2 * (kt & 1) + 0) * 4608];
        const __half*   V_ = &sKV[(2 * (kt & 1) + 1) * 4608];
        const unsigned* M_ = sM[kt & 1];

        // S = Q K^T  (already includes 0.125*log2e via q)
        float sc[8][4];
#pragma unroll
        for (int i = 0; i < 8; i++)
#pragma unroll
            for (int j = 0; j < 4; j++) sc[i][j] = 0.f;
#pragma unroll
        for (int kk = 0; kk < 4; kk++) {
#pragma unroll
            for (int nb = 0; nb < 4; nb++) {
                uint32_t kf[4];
                ldsm4(kf, &K_[(nb * 16 + (l % 8) + 8 * (l >> 4)) * 72 + kk * 16 + 8 * ((l >> 3) & 1)]);
                mma16816(sc[2 * nb + 0], qa[kk], kf[0], kf[1]);
                mma16816(sc[2 * nb + 1], qa[kk], kf[2], kf[3]);
            }
        }

        // constant-shift softmax: p = mask ? exp2(s) : 0; accumulate l
        unsigned ma0 = M_[ra_local * 2 + 0],       ma1 = M_[ra_local * 2 + 1];
        unsigned mb0 = M_[(ra_local + 8) * 2 + 0], mb1 = M_[(ra_local + 8) * 2 + 1];

        float sum_a = 0.f, sum_b = 0.f;
#pragma unroll
        for (int n8 = 0; n8 < 8; n8++) {
#pragma unroll
            for (int j = 0; j < 2; j++) {
                int col = n8 * 8 + t2 + j;
                unsigned wa = (col < 32) ? ma0 : ma1;
                unsigned wb = (col < 32) ? mb0 : mb1;
                float pa = ex2(sc[n8][j]);
                float pb = ex2(sc[n8][2 + j]);
                pa = ((wa >> (col & 31)) & 1) ? pa : 0.f;
                pb = ((wb >> (col & 31)) & 1) ? pb : 0.f;
                sc[n8][j] = pa;  sc[n8][2 + j] = pb;
                sum_a += pa;  sum_b += pb;
            }
        }
        l_a += sum_a;
        l_b += sum_b;

        uint32_t pa[4][4];
#pragma unroll
        for (int kk = 0; kk < 4; kk++) {
            pa[kk][0] = f2h2(sc[2 * kk][0], sc[2 * kk][1]);
            pa[kk][1] = f2h2(sc[2 * kk][2], sc[2 * kk][3]);
            pa[kk][2] = f2h2(sc[2 * kk + 1][0], sc[2 * kk + 1][1]);
            pa[kk][3] = f2h2(sc[2 * kk + 1][2], sc[2 * kk + 1][3]);
        }

#pragma unroll
        for (int kk = 0; kk < 4; kk++) {
#pragma unroll
            for (int nb = 0; nb < 4; nb++) {
                uint32_t vf[4];
                ldsm4t(vf, &V_[(kk * 16 + (l % 8) + 8 * ((l >> 3) & 1)) * 72 + nb * 16 + 8 * (l >> 4)]);
                mma16816(o[2 * nb + 0], pa[kk], vf[0], vf[1]);
                mma16816(o[2 * nb + 1], pa[kk], vf[2], vf[3]);
            }
        }
    }

    // lane-quad reduce of l (partial sums live on 4 lanes per row)
    l_a += __shfl_xor_sync(0xffffffffu, l_a, 1);
    l_a += __shfl_xor_sync(0xffffffffu, l_a, 2);
    l_b += __shfl_xor_sync(0xffffffffu, l_b, 1);
    l_b += __shfl_xor_sync(0xffffffffu, l_b, 2);

    float inv_a = (l_a > 0.f) ? 1.f / l_a : 0.f;
    float inv_b = (l_b > 0.f) ? 1.f / l_b : 0.f;
    int rowa = (b * SEQ + q0 + ra_local) * DMODEL + h * DH;
    int rowb = rowa + 8 * DMODEL;
#pragma unroll
    for (int n8 = 0; n8 < 8; n8++) {
        int c = n8 * 8 + t2;
        *reinterpret_cast<__half2*>(&g_ctx[rowa + c]) =
            __floats2half2_rn(o[n8][0] * inv_a, o[n8][1] * inv_a);
        *reinterpret_cast<__half2*>(&g_ctx[rowb + c]) =
            __floats2half2_rn(o[n8][2] * inv_b, o[n8][3] * inv_b);
    }
}

// ---------------------------------------------------------------- launch

extern "C" void kernel_launch(void* const* d_in, const int* in_sizes, int n_in,
                              void* d_out, int out_size)
{
    const float* Q    = (const float*)d_in[0];
    const float* K    = (const float*)d_in[1];
    const float* V    = (const float*)d_in[2];
    const int*   mask = (const int*)  d_in[3];
    const float* Wq   = (const float*)d_in[4];
    const float* bq   = (const float*)d_in[5];
    const float* Wk   = (const float*)d_in[6];
    const float* bk   = (const float*)d_in[7];
    const float* Wv   = (const float*)d_in[8];
    const float* bv   = (const float*)d_in[9];
    const float* Wo   = (const float*)d_in[10];
    const float* bo   = (const float*)d_in[11];
    float* out = (float*)d_out;

    __half *xq, *xk, *xv, *wq, *wk, *wv, *wo, *ctx;
    cudaGetSymbolAddress((void**)&xq, g_xq);
    cudaGetSymbolAddress((void**)&xk, g_xk);
    cudaGetSymbolAddress((void**)&xv, g_xv);
    cudaGetSymbolAddress((void**)&wq, g_wq);
    cudaGetSymbolAddress((void**)&wk, g_wk);
    cudaGetSymbolAddress((void**)&wv, g_wv);
    cudaGetSymbolAddress((void**)&wo, g_wo);
    cudaGetSymbolAddress((void**)&ctx, g_ctx);

    prep_kernel<<<6656, 256>>>(Q, K, V, Wq, Wk, Wv, Wo);

    qkv_kernel<<<dim3(ROWS / 128, DMODEL / 128, 4), 256>>>(
        mask, xq, xk, xv, wq, wk, wv, bq, bk, bv);

    attn_kernel<<<dim3(SEQ / 64, NH, BATCH), 128>>>();

    oproj_kernel<<<dim3(ROWS / 128, DMODEL / 128), 256>>>(ctx, wo, bo, out);
}

// round 17
// speedup vs baseline: 1.1092x; 1.0038x over previous
#include <cuda_runtime.h>
#include <cuda_fp16.h>
#include <cstdint>
#include <cfloat>

#define DEVI __device__ __forceinline__

static constexpr int BATCH  = 4;
static constexpr int SEQ    = 2048;
static constexpr int DMODEL = 512;
static constexpr int NH     = 8;
static constexpr int DH     = 64;
static constexpr int ROWS   = BATCH * SEQ;          // 8192

// Scratch (allocation-free rule: device globals)
__device__ __align__(16) __half   g_xq[ROWS * DMODEL];
__device__ __align__(16) __half   g_xk[ROWS * DMODEL];
__device__ __align__(16) __half   g_xv[ROWS * DMODEL];
__device__ __align__(16) __half   g_wq[DMODEL * DMODEL];
__device__ __align__(16) __half   g_wk[DMODEL * DMODEL];
__device__ __align__(16) __half   g_wv[DMODEL * DMODEL];
__device__ __align__(16) __half   g_wo[DMODEL * DMODEL];
__device__ __align__(16) __half   g_q[BATCH * NH * SEQ * DH];
__device__ __align__(16) __half   g_k[BATCH * NH * SEQ * DH];
__device__ __align__(16) __half   g_v[BATCH * NH * SEQ * DH];
__device__ __align__(16) __half   g_ctx[ROWS * DMODEL];
__device__            unsigned    g_maskp[BATCH * SEQ * (SEQ / 32)];

// ---------------------------------------------------------------- helpers

DEVI uint32_t smaddr(const void* p) { return (uint32_t)__cvta_generic_to_shared(p); }

DEVI void ldsm4(uint32_t r[4], const void* p) {
    uint32_t a = smaddr(p);
    asm volatile("ldmatrix.sync.aligned.m8n8.x4.shared.b16 {%0,%1,%2,%3}, [%4];"
                 : "=r"(r[0]), "=r"(r[1]), "=r"(r[2]), "=r"(r[3]) : "r"(a));
}
DEVI void ldsm4t(uint32_t r[4], const void* p) {
    uint32_t a = smaddr(p);
    asm volatile("ldmatrix.sync.aligned.m8n8.x4.trans.shared.b16 {%0,%1,%2,%3}, [%4];"
                 : "=r"(r[0]), "=r"(r[1]), "=r"(r[2]), "=r"(r[3]) : "r"(a));
}

DEVI void mma16816(float c[4], const uint32_t a[4], uint32_t b0, uint32_t b1) {
    asm volatile(
        "mma.sync.aligned.m16n8k16.row.col.f32.f16.f16.f32 "
        "{%0,%1,%2,%3}, {%4,%5,%6,%7}, {%8,%9}, {%0,%1,%2,%3};"
        : "+f"(c[0]), "+f"(c[1]), "+f"(c[2]), "+f"(c[3])
        : "r"(a[0]), "r"(a[1]), "r"(a[2]), "r"(a[3]), "r"(b0), "r"(b1));
}

DEVI uint32_t f2h2(float x, float y) {
    __half2 h = __floats2half2_rn(x, y);
    return *reinterpret_cast<uint32_t*>(&h);
}

DEVI float ex2(float x) {
    float y;
    asm("ex2.approx.ftz.f32 %0, %1;" : "=f"(y) : "f"(x));
    return y;
}

DEVI void cpa16(void* dst, const void* src) {
    asm volatile("cp.async.cg.shared.global [%0], [%1], 16;" :: "r"(smaddr(dst)), "l"(src));
}
DEVI void cpa4(void* dst, const void* src) {
    asm volatile("cp.async.ca.shared.global [%0], [%1], 4;" :: "r"(smaddr(dst)), "l"(src));
}
DEVI void cpcommit() { asm volatile("cp.async.commit_group;"); }
DEVI void cpwait0()  { asm volatile("cp.async.wait_group 0;"); }

// ---------------------------------------------------------------- prep: fp32->fp16 converts ONLY

__global__ __launch_bounds__(256) void prep_kernel(
    const float* __restrict__ Q, const float* __restrict__ K, const float* __restrict__ V,
    const float* __restrict__ Wq, const float* __restrict__ Wk,
    const float* __restrict__ Wv, const float* __restrict__ Wo)
{
    int blk = blockIdx.x;
    const float* src; __half* dst; int off;
    if      (blk < 2048) { src = Q;  dst = g_xq; off = blk; }
    else if (blk < 4096) { src = K;  dst = g_xk; off = blk - 2048; }
    else if (blk < 6144) { src = V;  dst = g_xv; off = blk - 4096; }
    else if (blk < 6272) { src = Wq; dst = g_wq; off = blk - 6144; }
    else if (blk < 6400) { src = Wk; dst = g_wk; off = blk - 6272; }
    else if (blk < 6528) { src = Wv; dst = g_wv; off = blk - 6400; }
    else                 { src = Wo; dst = g_wo; off = blk - 6528; }
    int base = off * 2048 + threadIdx.x * 8;
    float4 v0 = *reinterpret_cast<const float4*>(&src[base]);
    float4 v1 = *reinterpret_cast<const float4*>(&src[base + 4]);
    __half2 h[4] = { __floats2half2_rn(v0.x, v0.y), __floats2half2_rn(v0.z, v0.w),
                     __floats2half2_rn(v1.x, v1.y), __floats2half2_rn(v1.z, v1.w) };
    *reinterpret_cast<uint4*>(&dst[base]) = *reinterpret_cast<uint4*>(h);
}

// ---------------------------------------------------------------- QKV GEMM + mask pack (z = 0..2 gemm, z = 3 mask)
// OCCUPANCY: 128-thread CTAs, tile 64x128, 4 warps as 2m x 2n — the WARP tile
// stays 32x64 (16 MMAs per 6 ldsm, same as the 256-thread version), so the
// mma:ldsm ratio that sank R9 is preserved. regs ~100 -> ~5 CTAs/SM = 20 warps
// vs 16. z==3 slice (512 CTAs x 1024 words): mask pack overlapping GEMM.

__global__ __launch_bounds__(128) void qkv_kernel(
    const int* __restrict__ mask,
    const __half* __restrict__ A0, const __half* __restrict__ A1, const __half* __restrict__ A2,
    const __half* __restrict__ W0, const __half* __restrict__ W1, const __half* __restrict__ W2,
    const float* __restrict__ b0p, const float* __restrict__ b1p, const float* __restrict__ b2p)
{
    __shared__ __half sA[2][64 * 40];
    __shared__ __half sB[2][32 * 136];

    int tid = threadIdx.x, l = tid & 31, w = tid >> 5;
    int z = blockIdx.z;

    if (z == 3) {           // ---- mask packing slice: 512 CTAs x 1024 words
        int cta = blockIdx.x * 4 + blockIdx.y;          // 0..511
#pragma unroll
        for (int i = 0; i < 8; i++) {
            int wi = cta * 1024 + i * 128 + tid;
            const int4* p = reinterpret_cast<const int4*>(mask) + wi * 8;
            unsigned bits = 0;
#pragma unroll
            for (int j = 0; j < 8; j++) {
                int4 v = p[j];
                bits |= (v.x != 0 ? 1u : 0u) << (j * 4 + 0);
                bits |= (v.y != 0 ? 1u : 0u) << (j * 4 + 1);
                bits |= (v.z != 0 ? 1u : 0u) << (j * 4 + 2);
                bits |= (v.w != 0 ? 1u : 0u) << (j * 4 + 3);
            }
            g_maskp[wi] = bits;
        }
        return;
    }

    int wm = w >> 1, wn = w & 1;                       // 2m x 2n warps
    int m0 = blockIdx.x * 64, n0 = blockIdx.y * 128;
    const __half* A = (z == 0) ? A0 : (z == 1) ? A1 : A2;
    const __half* W = (z == 0) ? W0 : (z == 1) ? W1 : W2;
    const float* bias = (z == 0) ? b0p : (z == 1) ? b1p : b2p;

    float o[2][8][4];
#pragma unroll
    for (int mb = 0; mb < 2; mb++)
#pragma unroll
        for (int i = 0; i < 8; i++)
#pragma unroll
            for (int j = 0; j < 4; j++) o[mb][i][j] = 0.f;

    {  // prefetch stage 0: A 64x32 (256 u4, 2/thr), B 32x128 (512 u4, 4/thr)
#pragma unroll
        for (int i = 0; i < 2; i++) {
            int c = tid + i * 128; int r = c >> 2, cc = (c & 3) * 8;
            cpa16(&sA[0][r * 40 + cc], &A[(m0 + r) * 512 + cc]);
        }
#pragma unroll
        for (int i = 0; i < 4; i++) {
            int c = tid + i * 128; int r = c >> 4, cc = (c & 15) * 8;
            cpa16(&sB[0][r * 136 + cc], &W[r * 512 + n0 + cc]);
        }
        cpcommit();
    }

    for (int t = 0; t < 16; t++) {
        cpwait0();
        __syncthreads();
        if (t < 15) {
            int buf = (t + 1) & 1, t1 = t + 1;
#pragma unroll
            for (int i = 0; i < 2; i++) {
                int c = tid + i * 128; int r = c >> 2, cc = (c & 3) * 8;
                cpa16(&sA[buf][r * 40 + cc], &A[(m0 + r) * 512 + t1 * 32 + cc]);
            }
#pragma unroll
            for (int i = 0; i < 4; i++) {
                int c = tid + i * 128; int r = c >> 4, cc = (c & 15) * 8;
                cpa16(&sB[buf][r * 136 + cc], &W[(t1 * 32 + r) * 512 + n0 + cc]);
            }
            cpcommit();
        }
        const __half* a_ = sA[t & 1];
        const __half* b_ = sB[t & 1];
#pragma unroll
        for (int kk = 0; kk < 2; kk++) {
            uint32_t af[2][4];
#pragma unroll
            for (int mb = 0; mb < 2; mb++)
                ldsm4(af[mb], &a_[(wm * 32 + mb * 16 + (l % 16)) * 40 + kk * 16 + 8 * (l / 16)]);
#pragma unroll
            for (int nb = 0; nb < 4; nb++) {
                uint32_t bf[4];
                ldsm4t(bf, &b_[(kk * 16 + (l % 8) + 8 * ((l >> 3) & 1)) * 136 + wn * 64 + nb * 16 + 8 * (l >> 4)]);
#pragma unroll
                for (int mb = 0; mb < 2; mb++) {
                    mma16816(o[mb][2 * nb + 0], af[mb], bf[0], bf[1]);
                    mma16816(o[mb][2 * nb + 1], af[mb], bf[2], bf[3]);
                }
            }
        }
    }

    int t2 = (l & 3) * 2;
    __half* dst = (z == 0) ? g_q : (z == 1) ? g_k : g_v;
    float s = (z == 0) ? 0.1803368801111204f : 1.f;   // 1/sqrt(64)*log2(e) folded into q
    int h = (n0 + wn * 64) >> 6;
#pragma unroll
    for (int mb = 0; mb < 2; mb++) {
        int ra = m0 + wm * 32 + mb * 16 + (l >> 2);
        int rb = ra + 8;
        int ba = ra >> 11, sa = ra & 2047;
        int bb = rb >> 11, sb = rb & 2047;
#pragma unroll
        for (int n8 = 0; n8 < 8; n8++) {
            int c = n0 + wn * 64 + n8 * 8 + t2;
            int d = c & 63;
            float c0 = bias[c], c1 = bias[c + 1];
            int ia = (((ba << 3) + h) * SEQ + sa) * DH + d;
            int ib = (((bb << 3) + h) * SEQ + sb) * DH + d;
            *reinterpret_cast<__half2*>(&dst[ia]) =
                __floats2half2_rn((o[mb][n8][0] + c0) * s, (o[mb][n8][1] + c1) * s);
            *reinterpret_cast<__half2*>(&dst[ib]) =
                __floats2half2_rn((o[mb][n8][2] + c0) * s, (o[mb][n8][3] + c1) * s);
        }
    }
}

// ---------------------------------------------------------------- output projection
// Same 128-thread / 64x128-tile / 32x64-warp-tile layout.

__global__ __launch_bounds__(128) void oproj_kernel(
    const __half* __restrict__ A, const __half* __restrict__ W,
    const float* __restrict__ bias, float* __restrict__ outf)
{
    __shared__ __half sA[2][64 * 40];
    __shared__ __half sB[2][32 * 136];

    int tid = threadIdx.x, l = tid & 31, w = tid >> 5;
    int wm = w >> 1, wn = w & 1;
    int m0 = blockIdx.x * 64, n0 = blockIdx.y * 128;

    float o[2][8][4];
#pragma unroll
    for (int mb = 0; mb < 2; mb++)
#pragma unroll
        for (int i = 0; i < 8; i++)
#pragma unroll
            for (int j = 0; j < 4; j++) o[mb][i][j] = 0.f;

    {
#pragma unroll
        for (int i = 0; i < 2; i++) {
            int c = tid + i * 128; int r = c >> 2, cc = (c & 3) * 8;
            cpa16(&sA[0][r * 40 + cc], &A[(m0 + r) * 512 + cc]);
        }
#pragma unroll
        for (int i = 0; i < 4; i++) {
            int c = tid + i * 128; int r = c >> 4, cc = (c & 15) * 8;
            cpa16(&sB[0][r * 136 + cc], &W[r * 512 + n0 + cc]);
        }
        cpcommit();
    }

    for (int t = 0; t < 16; t++) {
        cpwait0();
        __syncthreads();
        if (t < 15) {
            int buf = (t + 1) & 1, t1 = t + 1;
#pragma unroll
            for (int i = 0; i < 2; i++) {
                int c = tid + i * 128; int r = c >> 2, cc = (c & 3) * 8;
                cpa16(&sA[buf][r * 40 + cc], &A[(m0 + r) * 512 + t1 * 32 + cc]);
            }
#pragma unroll
            for (int i = 0; i < 4; i++) {
                int c = tid + i * 128; int r = c >> 4, cc = (c & 15) * 8;
                cpa16(&sB[buf][r * 136 + cc], &W[(t1 * 32 + r) * 512 + n0 + cc]);
            }
            cpcommit();
        }
        const __half* a_ = sA[t & 1];
        const __half* b_ = sB[t & 1];
#pragma unroll
        for (int kk = 0; kk < 2; kk++) {
            uint32_t af[2][4];
#pragma unroll
            for (int mb = 0; mb < 2; mb++)
                ldsm4(af[mb], &a_[(wm * 32 + mb * 16 + (l % 16)) * 40 + kk * 16 + 8 * (l / 16)]);
#pragma unroll
            for (int nb = 0; nb < 4; nb++) {
                uint32_t bf[4];
                ldsm4t(bf, &b_[(kk * 16 + (l % 8) + 8 * ((l >> 3) & 1)) * 136 + wn * 64 + nb * 16 + 8 * (l >> 4)]);
#pragma unroll
                for (int mb = 0; mb < 2; mb++) {
                    mma16816(o[mb][2 * nb + 0], af[mb], bf[0], bf[1]);
                    mma16816(o[mb][2 * nb + 1], af[mb], bf[2], bf[3]);
                }
            }
        }
    }

    int t2 = (l & 3) * 2;
#pragma unroll
    for (int mb = 0; mb < 2; mb++) {
        int ra = m0 + wm * 32 + mb * 16 + (l >> 2);
        int rb = ra + 8;
#pragma unroll
        for (int n8 = 0; n8 < 8; n8++) {
            int c = n0 + wn * 64 + n8 * 8 + t2;
            float c0 = bias[c], c1 = bias[c + 1];
            *reinterpret_cast<float2*>(&outf[ra * 512 + c]) =
                make_float2(o[mb][n8][0] + c0, o[mb][n8][1] + c1);
            *reinterpret_cast<float2*>(&outf[rb * 512 + c]) =
                make_float2(o[mb][n8][2] + c0, o[mb][n8][3] + c1);
        }
    }
}

// ---------------------------------------------------------------- flash attention
// (unchanged from the R16 winner: 64 q rows, 128 threads, 3 CTAs/SM)

__global__ __launch_bounds__(128) void attn_kernel() {
    __shared__ __align__(16) __half sKV[4 * 64 * 72];   // 4608 halves per buffer
    __shared__ unsigned sM[2][128];

    int tid = threadIdx.x, l = tid & 31, w = tid >> 5;  // w in 0..3
    int q0 = blockIdx.x * 64, h = blockIdx.y, b = blockIdx.z;
    int bh = b * NH + h;
    const __half* gq = &g_q[(bh * SEQ + q0) * DH];

    __half* sQ = &sKV[2 * 4608];                        // aliases [K1]

#pragma unroll
    for (int i = 0; i < 4; i++) {
        int e = tid + i * 128;
        int r = e >> 3, c = (e & 7) * 8;
        *reinterpret_cast<uint4*>(&sQ[r * 72 + c]) =
            *reinterpret_cast<const uint4*>(&gq[r * 64 + c]);
    }

    {   // prefetch stage 0 (K0/V0 — disjoint from sQ alias)
        const __half* gk = &g_k[(bh * SEQ) * DH];
        const __half* gv = &g_v[(bh * SEQ) * DH];
#pragma unroll
        for (int i = 0; i < 4; i++) {
            int c = tid + i * 128; int r = c >> 3, cc = (c & 7) * 8;
            cpa16(&sKV[0 * 4608 + r * 72 + cc], &gk[r * 64 + cc]);
            cpa16(&sKV[1 * 4608 + r * 72 + cc], &gv[r * 64 + cc]);
        }
        cpa4(&sM[0][tid], &g_maskp[(b * SEQ + q0 + (tid >> 1)) * (SEQ / 32) + (tid & 1)]);
        cpcommit();
    }
    __syncthreads();   // sQ visible

    uint32_t qa[4][4];
#pragma unroll
    for (int kk = 0; kk < 4; kk++)
        ldsm4(qa[kk], &sQ[(w * 16 + (l % 16)) * 72 + kk * 16 + 8 * (l / 16)]);

    __syncthreads();   // all threads done reading sQ before anyone writes buf1

    float o[8][4];
#pragma unroll
    for (int i = 0; i < 8; i++)
#pragma unroll
        for (int j = 0; j < 4; j++) o[i][j] = 0.f;
    float l_a = 0.f, l_b = 0.f;

    int ra_local = w * 16 + (l >> 2);
    int t2 = (l & 3) * 2;

    for (int kt = 0; kt < 32; kt++) {
        cpwait0();
        __syncthreads();
        if (kt < 31) {
            int buf = (kt + 1) & 1;
            const __half* gk = &g_k[(bh * SEQ + (kt + 1) * 64) * DH];
            const __half* gv = &g_v[(bh * SEQ + (kt + 1) * 64) * DH];
#pragma unroll
            for (int i = 0; i < 4; i++) {
                int c = tid + i * 128; int r = c >> 3, cc = (c & 7) * 8;
                cpa16(&sKV[(2 * buf + 0) * 4608 + r * 72 + cc], &gk[r * 64 + cc]);
                cpa16(&sKV[(2 * buf + 1) * 4608 + r * 72 + cc], &gv[r * 64 + cc]);
            }
            cpa4(&sM[buf][tid],
                 &g_maskp[(b * SEQ + q0 + (tid >> 1)) * (SEQ / 32) + (kt + 1) * 2 + (tid & 1)]);
            cpcommit();
        }
        const __half*   K_ = &sKV[(2 * (kt & 1) + 0) * 4608];
        const __half*   V_ = &sKV[(2 * (kt & 1) + 1) * 4608];
        const unsigned* M_ = sM[kt & 1];

        // S = Q K^T  (already includes 0.125*log2e via q)
        float sc[8][4];
#pragma unroll
        for (int i = 0; i < 8; i++)
#pragma unroll
            for (int j = 0; j < 4; j++) sc[i][j] = 0.f;
#pragma unroll
        for (int kk = 0; kk < 4; kk++) {
#pragma unroll
            for (int nb = 0; nb < 4; nb++) {
                uint32_t kf[4];
                ldsm4(kf, &K_[(nb * 16 + (l % 8) + 8 * (l >> 4)) * 72 + kk * 16 + 8 * ((l >> 3) & 1)]);
                mma16816(sc[2 * nb + 0], qa[kk], kf[0], kf[1]);
                mma16816(sc[2 * nb + 1], qa[kk], kf[2], kf[3]);
            }
        }

        // constant-shift softmax: p = mask ? exp2(s) : 0; accumulate l
        unsigned ma0 = M_[ra_local * 2 + 0],       ma1 = M_[ra_local * 2 + 1];
        unsigned mb0 = M_[(ra_local + 8) * 2 + 0], mb1 = M_[(ra_local + 8) * 2 + 1];

        float sum_a = 0.f, sum_b = 0.f;
#pragma unroll
        for (int n8 = 0; n8 < 8; n8++) {
#pragma unroll
            for (int j = 0; j < 2; j++) {
                int col = n8 * 8 + t2 + j;
                unsigned wa = (col < 32) ? ma0 : ma1;
                unsigned wb = (col < 32) ? mb0 : mb1;
                float pa = ex2(sc[n8][j]);
                float pb = ex2(sc[n8][2 + j]);
                pa = ((wa >> (col & 31)) & 1) ? pa : 0.f;
                pb = ((wb >> (col & 31)) & 1) ? pb : 0.f;
                sc[n8][j] = pa;  sc[n8][2 + j] = pb;
                sum_a += pa;  sum_b += pb;
            }
        }
        l_a += sum_a;
        l_b += sum_b;

        uint32_t pa[4][4];
#pragma unroll
        for (int kk = 0; kk < 4; kk++) {
            pa[kk][0] = f2h2(sc[2 * kk][0], sc[2 * kk][1]);
            pa[kk][1] = f2h2(sc[2 * kk][2], sc[2 * kk][3]);
            pa[kk][2] = f2h2(sc[2 * kk + 1][0], sc[2 * kk + 1][1]);
            pa[kk][3] = f2h2(sc[2 * kk + 1][2], sc[2 * kk + 1][3]);
        }

#pragma unroll
        for (int kk = 0; kk < 4; kk++) {
#pragma unroll
            for (int nb = 0; nb < 4; nb++) {
                uint32_t vf[4];
                ldsm4t(vf, &V_[(kk * 16 + (l % 8) + 8 * ((l >> 3) & 1)) * 72 + nb * 16 + 8 * (l >> 4)]);
                mma16816(o[2 * nb + 0], pa[kk], vf[0], vf[1]);
                mma16816(o[2 * nb + 1], pa[kk], vf[2], vf[3]);
            }
        }
    }

    // lane-quad reduce of l (partial sums live on 4 lanes per row)
    l_a += __shfl_xor_sync(0xffffffffu, l_a, 1);
    l_a += __shfl_xor_sync(0xffffffffu, l_a, 2);
    l_b += __shfl_xor_sync(0xffffffffu, l_b, 1);
    l_b += __shfl_xor_sync(0xffffffffu, l_b, 2);

    float inv_a = (l_a > 0.f) ? 1.f / l_a : 0.f;
    float inv_b = (l_b > 0.f) ? 1.f / l_b : 0.f;
    int rowa = (b * SEQ + q0 + ra_local) * DMODEL + h * DH;
    int rowb = rowa + 8 * DMODEL;
#pragma unroll
    for (int n8 = 0; n8 < 8; n8++) {
        int c = n8 * 8 + t2;
        *reinterpret_cast<__half2*>(&g_ctx[rowa + c]) =
            __floats2half2_rn(o[n8][0] * inv_a, o[n8][1] * inv_a);
        *reinterpret_cast<__half2*>(&g_ctx[rowb + c]) =
            __floats2half2_rn(o[n8][2] * inv_b, o[n8][3] * inv_b);
    }
}

// ---------------------------------------------------------------- launch

extern "C" void kernel_launch(void* const* d_in, const int* in_sizes, int n_in,
                              void* d_out, int out_size)
{
    const float* Q    = (const float*)d_in[0];
    const float* K    = (const float*)d_in[1];
    const float* V    = (const float*)d_in[2];
    const int*   mask = (const int*)  d_in[3];
    const float* Wq   = (const float*)d_in[4];
    const float* bq   = (const float*)d_in[5];
    const float* Wk   = (const float*)d_in[6];
    const float* bk   = (const float*)d_in[7];
    const float* Wv   = (const float*)d_in[8];
    const float* bv   = (const float*)d_in[9];
    const float* Wo   = (const float*)d_in[10];
    const float* bo   = (const float*)d_in[11];
    float* out = (float*)d_out;

    __half *xq, *xk, *xv, *wq, *wk, *wv, *wo, *ctx;
    cudaGetSymbolAddress((void**)&xq, g_xq);
    cudaGetSymbolAddress((void**)&xk, g_xk);
    cudaGetSymbolAddress((void**)&xv, g_xv);
    cudaGetSymbolAddress((void**)&wq, g_wq);
    cudaGetSymbolAddress((void**)&wk, g_wk);
    cudaGetSymbolAddress((void**)&wv, g_wv);
    cudaGetSymbolAddress((void**)&wo, g_wo);
    cudaGetSymbolAddress((void**)&ctx, g_ctx);

    prep_kernel<<<6656, 256>>>(Q, K, V, Wq, Wk, Wv, Wo);

    qkv_kernel<<<dim3(ROWS / 64, DMODEL / 128, 4), 128>>>(
        mask, xq, xk, xv, wq, wk, wv, bq, bk, bv);

    attn_kernel<<<dim3(SEQ / 64, NH, BATCH), 128>>>();

    oproj_kernel<<<dim3(ROWS / 64, DMODEL / 128), 128>>>(ctx, wo, bo, out);
}